// round 5
// baseline (speedup 1.0000x reference)
#include <cuda_runtime.h>
#include <cstdint>

#define VV 8000
#define DD 128
#define UU 256
#define BB 32
#define SS 256
#define H3 768
#define H6 1536
#define MR 8192   // B*S

// ---------------- scratch (static device allocations; no cudaMalloc) ---------
__device__ float g_embw[VV * H6];     // (emb @ [W_f|W_b]) + [b_f0|b_b0]  [8000,1536]
__device__ float g_wcat[DD * H6];     // [W_f | W_b] concat along N
__device__ float g_bcat[H6];          // [b_f[0] | b_b[0]]
__device__ float g_hcat[MR * 2 * UU];
__device__ float g_wf[2 * UU * VV];   // fused weight W1@W2 [512, 8000]
__device__ float g_bf[VV];            // fused bias b1@W2 + b2
__device__ float g_bpart[32 * VV];    // bias partial sums
__device__ float g_zb[VV];            // zero bias (never written; zero-init)

__device__ __forceinline__ float rna_tf32(float x) {
    uint32_t u;
    asm("cvt.rna.tf32.f32 %0, %1;" : "=r"(u) : "f"(x));
    return __uint_as_float(u);
}
__device__ __forceinline__ uint32_t rna_tf32_u(uint32_t x) {
    uint32_t u;
    asm("cvt.rna.tf32.f32 %0, %1;" : "=r"(u) : "r"(x));
    return u;
}

// packed f32x2 helpers (sm_103a)
__device__ __forceinline__ unsigned long long pack2(float x, float y) {
    unsigned long long r;
    asm("mov.b64 %0, {%1,%2};" : "=l"(r) : "f"(x), "f"(y));
    return r;
}
__device__ __forceinline__ float2 unpack2(unsigned long long v) {
    float2 r;
    asm("mov.b64 {%0,%1}, %2;" : "=f"(r.x), "=f"(r.y) : "l"(v));
    return r;
}
#define FMA2(acc, a, b) \
    asm("fma.rn.f32x2 %0, %1, %2, %0;" : "+l"(acc) : "l"(a), "l"(b))

// ---------------- build [W_f|W_b] and [b_f0|b_b0] -----------------------------
__global__ void build_wcat(const float* __restrict__ Wf_, const float* __restrict__ Wb_,
                           const float* __restrict__ bf_, const float* __restrict__ bb_,
                           float* __restrict__ wcat, float* __restrict__ bcat) {
    int i = blockIdx.x * 256 + threadIdx.x;
    if (i < DD * H6) {
        int k = i / H6, j = i % H6;
        wcat[i] = (j < H3) ? Wf_[k * H3 + j] : Wb_[k * H3 + (j - H3)];
    }
    if (i < H6)
        bcat[i] = (i < H3) ? bf_[i] : bb_[i - H3];
}

// ---------------- fused bias: bf[n] = b2[n] + sum_v b1[v]*W2[v][n] ------------
__global__ void bias_fuse_part(const float* __restrict__ b1v, const float* __restrict__ W2m,
                               float* __restrict__ part) {
    int n = blockIdx.x * 128 + threadIdx.x;
    if (n >= VV) return;
    int v0 = blockIdx.y * 250;
    float acc = 0.f;
#pragma unroll 5
    for (int v = v0; v < v0 + 250; v++)
        acc += b1v[v] * W2m[(size_t)v * VV + n];
    part[blockIdx.y * VV + n] = acc;
}
__global__ void bias_fuse_reduce(const float* __restrict__ part, const float* __restrict__ b2v,
                                 float* __restrict__ bf) {
    int n = blockIdx.x * 128 + threadIdx.x;
    if (n >= VV) return;
    float acc = b2v[n];
#pragma unroll
    for (int y = 0; y < 32; y++) acc += part[y * VV + n];
    bf[n] = acc;
}

// ---------------- tf32 GEMM: C[M,N] = A[M,K] @ B[K,N] + bias[N] --------------
// 3-stage cp.async pipeline, one __syncthreads per k-tile.
// RA/RB: rna-round A/B fragments at smem load. RO: round output to tf32.
#define BM 128
#define BN 128
#define BKK 16
#define AST 20    // A smem row stride (floats) -> conflict-free fragment loads
#define BST 136   // B smem row stride (floats) -> conflict-free fragment loads
#define ASZ (BM * AST)
#define BSZ (BKK * BST)
#define GEMM_SMEM (3 * (ASZ + BSZ) * 4)

template <int RA, int RB, int RO>
__global__ void __launch_bounds__(256) gemm_tf32(
    const float* __restrict__ A, const float* __restrict__ Bm,
    const float* __restrict__ bias, float* __restrict__ C,
    int M, int N, int K)
{
    extern __shared__ __align__(16) float sm[];
    float* Asm = sm;               // 3 * ASZ
    float* Bsm = sm + 3 * ASZ;     // 3 * BSZ

    const int nbx = (N + BN - 1) / BN;
    const int nby = (M + BM - 1) / BM;
    const int CW = 16;                     // N-chunk width for L2-friendly raster
    int bid = blockIdx.x;
    int per = CW * nby;
    int chunk = bid / per;
    int rem = bid - chunk * per;
    int cw = min(CW, nbx - chunk * CW);
    int by = rem / cw;
    int bx = chunk * CW + (rem - by * cw);
    int m0 = by * BM, n0 = bx * BN;

    int tid = threadIdx.x;
    int lane = tid & 31;
    int wid = tid >> 5;
    int wm = wid >> 2;   // 0..1  (64 rows per warp)
    int wn = wid & 3;    // 0..3  (32 cols per warp)

    uint32_t sA = (uint32_t)__cvta_generic_to_shared(Asm);
    uint32_t sB = (uint32_t)__cvta_generic_to_shared(Bsm);

    int arow0 = tid >> 2;              int acc0c = (tid & 3) * 4;
    int arow1 = (tid + 256) >> 2;
    int brow0 = tid >> 5;              int bcc0 = (tid & 31) * 4;
    int brow1 = (tid + 256) >> 5;

    // clamped A rows (M-guard; OOB rows read row M-1, stores guarded)
    int ra0 = m0 + arow0; if (ra0 >= M) ra0 = M - 1;
    int ra1 = m0 + arow1; if (ra1 >= M) ra1 = M - 1;

    float acc[4][4][4];
#pragma unroll
    for (int a = 0; a < 4; a++)
#pragma unroll
        for (int b = 0; b < 4; b++)
#pragma unroll
            for (int c = 0; c < 4; c++) acc[a][b][c] = 0.f;

    const int KT = K / BKK;

    auto issue = [&](int kt, int buf) {
        int k0 = kt * BKK;
        {
            const float* g0 = A + (size_t)ra0 * K + k0 + acc0c;
            const float* g1 = A + (size_t)ra1 * K + k0 + acc0c;
            uint32_t d0 = sA + (uint32_t)(buf * ASZ + arow0 * AST + acc0c) * 4u;
            uint32_t d1 = sA + (uint32_t)(buf * ASZ + arow1 * AST + acc0c) * 4u;
            asm volatile("cp.async.cg.shared.global [%0],[%1],16;\n" :: "r"(d0), "l"(g0));
            asm volatile("cp.async.cg.shared.global [%0],[%1],16;\n" :: "r"(d1), "l"(g1));
        }
        {
            int n0c = n0 + bcc0;
            int gcol = (n0c < N) ? n0c : (N - 4);
            int sz = (n0c < N) ? 16 : 0;   // zero-fill OOB columns
            const float* g0 = Bm + (size_t)(k0 + brow0) * N + gcol;
            const float* g1 = Bm + (size_t)(k0 + brow1) * N + gcol;
            uint32_t d0 = sB + (uint32_t)(buf * BSZ + brow0 * BST + bcc0) * 4u;
            uint32_t d1 = sB + (uint32_t)(buf * BSZ + brow1 * BST + bcc0) * 4u;
            asm volatile("cp.async.cg.shared.global [%0],[%1],16,%2;\n" :: "r"(d0), "l"(g0), "r"(sz));
            asm volatile("cp.async.cg.shared.global [%0],[%1],16,%2;\n" :: "r"(d1), "l"(g1), "r"(sz));
        }
    };

    auto docompute = [&](int buf) {
        const float* Ab = Asm + buf * ASZ;
        const float* Bb = Bsm + buf * BSZ;
#pragma unroll
        for (int kk = 0; kk < 2; kk++) {
            uint32_t af[4][4];
#pragma unroll
            for (int mi = 0; mi < 4; mi++) {
                int r = wm * 64 + mi * 16 + (lane >> 2);
                int c = kk * 8 + (lane & 3);
                af[mi][0] = __float_as_uint(Ab[r * AST + c]);
                af[mi][1] = __float_as_uint(Ab[(r + 8) * AST + c]);
                af[mi][2] = __float_as_uint(Ab[r * AST + c + 4]);
                af[mi][3] = __float_as_uint(Ab[(r + 8) * AST + c + 4]);
                if (RA) {
                    af[mi][0] = rna_tf32_u(af[mi][0]);
                    af[mi][1] = rna_tf32_u(af[mi][1]);
                    af[mi][2] = rna_tf32_u(af[mi][2]);
                    af[mi][3] = rna_tf32_u(af[mi][3]);
                }
            }
            uint32_t bf[4][2];
#pragma unroll
            for (int ni = 0; ni < 4; ni++) {
                int cc = wn * 32 + ni * 8 + (lane >> 2);
                int kb = kk * 8 + (lane & 3);
                bf[ni][0] = __float_as_uint(Bb[kb * BST + cc]);
                bf[ni][1] = __float_as_uint(Bb[(kb + 4) * BST + cc]);
                if (RB) {
                    bf[ni][0] = rna_tf32_u(bf[ni][0]);
                    bf[ni][1] = rna_tf32_u(bf[ni][1]);
                }
            }
#pragma unroll
            for (int mi = 0; mi < 4; mi++)
#pragma unroll
                for (int ni = 0; ni < 4; ni++) {
                    asm volatile(
                        "mma.sync.aligned.m16n8k8.row.col.f32.tf32.tf32.f32 "
                        "{%0,%1,%2,%3},{%4,%5,%6,%7},{%8,%9},{%0,%1,%2,%3};\n"
                        : "+f"(acc[mi][ni][0]), "+f"(acc[mi][ni][1]),
                          "+f"(acc[mi][ni][2]), "+f"(acc[mi][ni][3])
                        : "r"(af[mi][0]), "r"(af[mi][1]), "r"(af[mi][2]), "r"(af[mi][3]),
                          "r"(bf[ni][0]), "r"(bf[ni][1]));
                }
        }
    };

    // prologue: 2 stages in flight
    issue(0, 0);
    asm volatile("cp.async.commit_group;\n");
    issue(1, 1);
    asm volatile("cp.async.commit_group;\n");

#pragma unroll 1
    for (int kt = 0; kt < KT; kt++) {
        if (kt + 1 < KT) {
            asm volatile("cp.async.wait_group 1;\n");
        } else {
            asm volatile("cp.async.wait_group 0;\n");
        }
        __syncthreads();
        if (kt + 2 < KT) {
            issue(kt + 2, (kt + 2) % 3);
            asm volatile("cp.async.commit_group;\n");
        }
        docompute(kt % 3);
    }

    // epilogue
#pragma unroll
    for (int mi = 0; mi < 4; mi++) {
        int r = m0 + wm * 64 + mi * 16 + (lane >> 2);
#pragma unroll
        for (int ni = 0; ni < 4; ni++) {
            int c = n0 + wn * 32 + ni * 8 + (lane & 3) * 2;
            if (c < N && r < M) {
                float b0v = bias[c], b1v = bias[c + 1];
                float v0 = acc[mi][ni][0] + b0v;
                float v1 = acc[mi][ni][1] + b1v;
                float v2 = acc[mi][ni][2] + b0v;
                float v3 = acc[mi][ni][3] + b1v;
                if (RO) {
                    v0 = rna_tf32(v0); v1 = rna_tf32(v1);
                    v2 = rna_tf32(v2); v3 = rna_tf32(v3);
                }
                *reinterpret_cast<float2*>(&C[(size_t)r * N + c]) = make_float2(v0, v1);
                if (r + 8 < M)
                    *reinterpret_cast<float2*>(&C[(size_t)(r + 8) * N + c]) = make_float2(v2, v3);
            }
        }
    }
}

// ---------------- bidirectional masked GRU scan (k-split, 768 thr) -----------
// grid (16, 2). xz gate rows gathered directly from embW[token] (latency hidden
// under the matvec). Thread (kc = tid/192, ct = tid%192): kc owns k-range,
// ct owns 4 contiguous output columns. Partials reduced through smem.
__global__ void __launch_bounds__(768) gru_scan(
    const float* __restrict__ embW,      // [8000][1536] = [f gates | b gates]
    const float* __restrict__ Uf, const float* __restrict__ Ub,
    const float* __restrict__ bf1, const float* __restrict__ bb1,
    const int* __restrict__ tokens, float* __restrict__ hcat)
{
    int dir = blockIdx.y;
    const float* Um = dir ? Ub : Uf;    // [256][768] native
    const float* bv = dir ? bb1 : bf1;  // b[1] row (768)
    int b0 = blockIdx.x * 2;
    int tid = threadIdx.x;
    int kc = tid / 192;        // 0..3
    int ct = tid % 192;        // 0..191

    __shared__ __align__(16) unsigned long long hsd[2][UU];  // (h,h) duplicated
    __shared__ __align__(16) float part[8][H3];              // [kc*2+b][col]

    // update-phase identity
    int ub = tid >> 8;         // 0..2 ; valid when tid < 512
    int uj = tid & 255;
    float bz = 0.f, br = 0.f, bh = 0.f;
    if (tid < 512) {
        bz = bv[uj]; br = bv[UU + uj]; bh = bv[2 * UU + uj];
        hsd[ub][uj] = 0ull;
    }
    __syncthreads();

    const ulonglong2* U2 = reinterpret_cast<const ulonglong2*>(Um);
    int k0 = kc * 64;

    for (int i = 0; i < SS; i++) {
        int s = dir ? (SS - 1 - i) : i;
        size_t rr[2];
        rr[0] = (size_t)b0 * SS + s;
        rr[1] = rr[0] + SS;

        // gather this step's gate row from embW[token] (overlaps matvec)
        float pz = 0.f, pr = 0.f, ph = 0.f; int tk = 1;
        if (tid < 512) {
            tk = tokens[rr[ub]];
            const float* xr = embW + (size_t)tk * H6 + dir * H3;
            pz = xr[uj]; pr = xr[UU + uj]; ph = xr[2 * UU + uj];
        }

        // ---- partial matvec over k-range [k0, k0+64) ----
        {
            unsigned long long a00 = 0, a01 = 0, a10 = 0, a11 = 0;
            const ulonglong2* h0 = reinterpret_cast<const ulonglong2*>(hsd[0]) + (k0 >> 1);
            const ulonglong2* h1 = reinterpret_cast<const ulonglong2*>(hsd[1]) + (k0 >> 1);
            const ulonglong2* up = U2 + (size_t)k0 * 192 + ct;
#pragma unroll 4
            for (int kk = 0; kk < 32; kk++) {
                ulonglong2 uA = up[0];
                ulonglong2 uB = up[192];
                up += 384;
                ulonglong2 hA = h0[kk];
                ulonglong2 hB = h1[kk];
                FMA2(a00, uA.x, hA.x); FMA2(a01, uA.y, hA.x);
                FMA2(a10, uA.x, hB.x); FMA2(a11, uA.y, hB.x);
                FMA2(a00, uB.x, hA.y); FMA2(a01, uB.y, hA.y);
                FMA2(a10, uB.x, hB.y); FMA2(a11, uB.y, hB.y);
            }
            float2 p00 = unpack2(a00), p01 = unpack2(a01);
            float2 p10 = unpack2(a10), p11 = unpack2(a11);
            reinterpret_cast<float4*>(part[kc * 2 + 0])[ct] = make_float4(p00.x, p00.y, p01.x, p01.y);
            reinterpret_cast<float4*>(part[kc * 2 + 1])[ct] = make_float4(p10.x, p10.y, p11.x, p11.y);
        }
        __syncthreads();

        // ---- reduce partials + gate update (threads 0..511) ----
        if (tid < 512) {
            float iz = part[0 + ub][uj]           + part[2 + ub][uj]
                     + part[4 + ub][uj]           + part[6 + ub][uj];
            float ir = part[0 + ub][UU + uj]      + part[2 + ub][UU + uj]
                     + part[4 + ub][UU + uj]      + part[6 + ub][UU + uj];
            float ih = part[0 + ub][2 * UU + uj]  + part[2 + ub][2 * UU + uj]
                     + part[4 + ub][2 * UU + uj]  + part[6 + ub][2 * UU + uj];

            float hold = ((const float*)&hsd[ub][uj])[0];
            float z = 1.f / (1.f + expf(-(pz + iz + bz)));
            float g = 1.f / (1.f + expf(-(pr + ir + br)));
            float c = tanhf(ph + g * (ih + bh));
            float hn = z * hold + (1.f - z) * c;
            if (tk == 0) hn = hold;

            hsd[ub][uj] = pack2(hn, hn);
            hcat[rr[ub] * (2 * UU) + dir * UU + uj] = rna_tf32(hn);
        }
        __syncthreads();
    }
}

// ---------------- host launcher ----------------------------------------------
extern "C" void kernel_launch(void* const* d_in, const int* in_sizes, int n_in,
                              void* d_out, int out_size)
{
    const int*   tokens = (const int*)d_in[0];
    const float* emb    = (const float*)d_in[1];
    const float* W_f    = (const float*)d_in[2];
    const float* U_f    = (const float*)d_in[3];
    const float* b_f    = (const float*)d_in[4];
    const float* W_b    = (const float*)d_in[5];
    const float* U_b    = (const float*)d_in[6];
    const float* b_b    = (const float*)d_in[7];
    const float* W1     = (const float*)d_in[8];
    const float* b1     = (const float*)d_in[9];
    const float* W2     = (const float*)d_in[10];
    const float* b2     = (const float*)d_in[11];
    float* out = (float*)d_out;

    float *embw, *wcat, *bcat, *hcat, *wf, *bfv, *bpart, *zb;
    cudaGetSymbolAddress((void**)&embw,  g_embw);
    cudaGetSymbolAddress((void**)&wcat,  g_wcat);
    cudaGetSymbolAddress((void**)&bcat,  g_bcat);
    cudaGetSymbolAddress((void**)&hcat,  g_hcat);
    cudaGetSymbolAddress((void**)&wf,    g_wf);
    cudaGetSymbolAddress((void**)&bfv,   g_bf);
    cudaGetSymbolAddress((void**)&bpart, g_bpart);
    cudaGetSymbolAddress((void**)&zb,    g_zb);

    // opt into 56.8KB dynamic smem for the GEMM instantiations
    cudaFuncSetAttribute(gemm_tf32<1,1,0>, cudaFuncAttributeMaxDynamicSharedMemorySize, GEMM_SMEM);
    cudaFuncSetAttribute(gemm_tf32<1,1,1>, cudaFuncAttributeMaxDynamicSharedMemorySize, GEMM_SMEM);
    cudaFuncSetAttribute(gemm_tf32<0,0,0>, cudaFuncAttributeMaxDynamicSharedMemorySize, GEMM_SMEM);

    // 1) concat weights/biases for the embedding projection
    build_wcat<<<(DD * H6 + 255) / 256, 256>>>(W_f, W_b, b_f, b_b, wcat, bcat);

    // 2) embW = rna(emb) @ rna([W_f|W_b]) + [b_f0|b_b0]   [8000, 1536]
    {
        int nbx = H6 / BN;                       // 12
        int nby = (VV + BM - 1) / BM;            // 63
        gemm_tf32<1,1,0><<<nbx * nby, 256, GEMM_SMEM>>>(emb, wcat, bcat, embw, VV, H6, DD);
    }

    // 3) fused output weight: Wf = rna(W1) @ rna(W2), rounded output
    {
        int nbx = (VV + BN - 1) / BN;            // 63
        int nby = (2 * UU) / BM;                 // 4
        gemm_tf32<1,1,1><<<nbx * nby, 256, GEMM_SMEM>>>(W1, W2, zb, wf, 2 * UU, VV, VV);
    }
    // fused bias: bf = b1 @ W2 + b2 (exact fp32, K split 32 ways)
    bias_fuse_part<<<dim3((VV + 127) / 128, 32), 128>>>(b1, W2, bpart);
    bias_fuse_reduce<<<(VV + 127) / 128, 128>>>(bpart, b2, bfv);

    // 4) bidirectional GRU scan (inline embW gather)
    gru_scan<<<dim3(BB / 2, 2), 768>>>(embw, U_f, U_b, b_f + H3, b_b + H3,
                                       tokens, hcat);

    // 5) logits = hcat @ Wf + bf -> output
    {
        int nbx = (VV + BN - 1) / BN, nby = MR / BM;  // 63 x 64
        gemm_tf32<0,0,0><<<nbx * nby, 256, GEMM_SMEM>>>(hcat, wf, bfv, out, MR, VV, 2 * UU);
    }
}

// round 6
// speedup vs baseline: 1.7453x; 1.7453x over previous
#include <cuda_runtime.h>
#include <cstdint>

#define VV 8000
#define DD 128
#define UU 256
#define BB 32
#define SS 256
#define H3 768
#define H6 1536
#define MR 8192   // B*S

// ---------------- scratch (static device allocations; no cudaMalloc) ---------
__device__ float g_embw[VV * H6];     // (emb @ [W_f|W_b]) + [b_f0|b_b0]  [8000,1536]
__device__ float g_wcat[DD * H6];     // [W_f | W_b] concat along N
__device__ float g_bcat[H6];          // [b_f[0] | b_b[0]]
__device__ float g_hcat[MR * 2 * UU];
__device__ float g_wf[2 * UU * VV];   // fused weight W1@W2 [512, 8000]
__device__ float g_bf[VV];            // fused bias b1@W2 + b2
__device__ float g_bpart[32 * VV];    // bias partial sums
__device__ float g_zb[VV];            // zero bias (never written; zero-init)
__device__ float g_uperm[2 * 4 * UU * 192];  // permuted U slices per (dir, rank)

__device__ __forceinline__ float rna_tf32(float x) {
    uint32_t u;
    asm("cvt.rna.tf32.f32 %0, %1;" : "=r"(u) : "f"(x));
    return __uint_as_float(u);
}
__device__ __forceinline__ uint32_t rna_tf32_u(uint32_t x) {
    uint32_t u;
    asm("cvt.rna.tf32.f32 %0, %1;" : "=r"(u) : "r"(x));
    return u;
}

// packed f32x2 helpers (sm_103a)
__device__ __forceinline__ unsigned long long pack2(float x, float y) {
    unsigned long long r;
    asm("mov.b64 %0, {%1,%2};" : "=l"(r) : "f"(x), "f"(y));
    return r;
}
__device__ __forceinline__ float2 unpack2(unsigned long long v) {
    float2 r;
    asm("mov.b64 {%0,%1}, %2;" : "=f"(r.x), "=f"(r.y) : "l"(v));
    return r;
}
#define FMA2(acc, a, b) \
    asm("fma.rn.f32x2 %0, %1, %2, %0;" : "+l"(acc) : "l"(a), "l"(b))

// DSMEM helpers
__device__ __forceinline__ uint32_t mapa_u32(uint32_t laddr, uint32_t rank) {
    uint32_t r;
    asm("mapa.shared::cluster.u32 %0, %1, %2;" : "=r"(r) : "r"(laddr), "r"(rank));
    return r;
}
__device__ __forceinline__ void st_cluster_u64(uint32_t addr, unsigned long long v) {
    asm volatile("st.shared::cluster.u64 [%0], %1;" :: "r"(addr), "l"(v) : "memory");
}
#define CLUSTER_ARRIVE() asm volatile("barrier.cluster.arrive.aligned;" ::: "memory")
#define CLUSTER_WAIT()   asm volatile("barrier.cluster.wait.aligned;" ::: "memory")

// ---------------- build [W_f|W_b] and [b_f0|b_b0] -----------------------------
__global__ void build_wcat(const float* __restrict__ Wf_, const float* __restrict__ Wb_,
                           const float* __restrict__ bf_, const float* __restrict__ bb_,
                           float* __restrict__ wcat, float* __restrict__ bcat) {
    int i = blockIdx.x * 256 + threadIdx.x;
    if (i < DD * H6) {
        int k = i / H6, j = i % H6;
        wcat[i] = (j < H3) ? Wf_[k * H3 + j] : Wb_[k * H3 + (j - H3)];
    }
    if (i < H6)
        bcat[i] = (i < H3) ? bf_[i] : bb_[i - H3];
}

// ---------------- permute U columns into per-(dir,rank) gate-triple slices ----
// slice[dir][r][k][c]: c<64 -> z col 64r+c ; c<128 -> r col 256+64r+(c-64) ;
//                      c<192 -> h col 512+64r+(c-128)
__global__ void permute_u(const float* __restrict__ Uf, const float* __restrict__ Ub,
                          float* __restrict__ uperm) {
    int idx = blockIdx.x * 256 + threadIdx.x;
    if (idx >= 2 * 4 * UU * 192) return;
    int c = idx % 192;
    int k = (idx / 192) % UU;
    int r = (idx / (192 * UU)) % 4;
    int dir = idx / (192 * UU * 4);
    const float* Um = dir ? Ub : Uf;
    int col = (c < 64) ? (64 * r + c)
            : (c < 128) ? (UU + 64 * r + (c - 64))
                        : (2 * UU + 64 * r + (c - 128));
    uperm[idx] = Um[k * H3 + col];
}

// ---------------- fused bias: bf[n] = b2[n] + sum_v b1[v]*W2[v][n] ------------
__global__ void bias_fuse_part(const float* __restrict__ b1v, const float* __restrict__ W2m,
                               float* __restrict__ part) {
    int n = blockIdx.x * 128 + threadIdx.x;
    if (n >= VV) return;
    int v0 = blockIdx.y * 250;
    float acc = 0.f;
#pragma unroll 5
    for (int v = v0; v < v0 + 250; v++)
        acc += b1v[v] * W2m[(size_t)v * VV + n];
    part[blockIdx.y * VV + n] = acc;
}
__global__ void bias_fuse_reduce(const float* __restrict__ part, const float* __restrict__ b2v,
                                 float* __restrict__ bf) {
    int n = blockIdx.x * 128 + threadIdx.x;
    if (n >= VV) return;
    float acc = b2v[n];
#pragma unroll
    for (int y = 0; y < 32; y++) acc += part[y * VV + n];
    bf[n] = acc;
}

// ---------------- tf32 GEMM: C[M,N] = A[M,K] @ B[K,N] + bias[N] --------------
#define BM 128
#define BN 128
#define BKK 16
#define AST 20
#define BST 136
#define ASZ (BM * AST)
#define BSZ (BKK * BST)
#define GEMM_SMEM (3 * (ASZ + BSZ) * 4)

template <int RA, int RB, int RO>
__global__ void __launch_bounds__(256) gemm_tf32(
    const float* __restrict__ A, const float* __restrict__ Bm,
    const float* __restrict__ bias, float* __restrict__ C,
    int M, int N, int K)
{
    extern __shared__ __align__(16) float sm[];
    float* Asm = sm;
    float* Bsm = sm + 3 * ASZ;

    const int nbx = (N + BN - 1) / BN;
    const int nby = (M + BM - 1) / BM;
    const int CW = 16;
    int bid = blockIdx.x;
    int per = CW * nby;
    int chunk = bid / per;
    int rem = bid - chunk * per;
    int cw = min(CW, nbx - chunk * CW);
    int by = rem / cw;
    int bx = chunk * CW + (rem - by * cw);
    int m0 = by * BM, n0 = bx * BN;

    int tid = threadIdx.x;
    int lane = tid & 31;
    int wid = tid >> 5;
    int wm = wid >> 2;
    int wn = wid & 3;

    uint32_t sA = (uint32_t)__cvta_generic_to_shared(Asm);
    uint32_t sB = (uint32_t)__cvta_generic_to_shared(Bsm);

    int arow0 = tid >> 2;              int acc0c = (tid & 3) * 4;
    int arow1 = (tid + 256) >> 2;
    int brow0 = tid >> 5;              int bcc0 = (tid & 31) * 4;
    int brow1 = (tid + 256) >> 5;

    int ra0 = m0 + arow0; if (ra0 >= M) ra0 = M - 1;
    int ra1 = m0 + arow1; if (ra1 >= M) ra1 = M - 1;

    float acc[4][4][4];
#pragma unroll
    for (int a = 0; a < 4; a++)
#pragma unroll
        for (int b = 0; b < 4; b++)
#pragma unroll
            for (int c = 0; c < 4; c++) acc[a][b][c] = 0.f;

    const int KT = K / BKK;

    auto issue = [&](int kt, int buf) {
        int k0 = kt * BKK;
        {
            const float* g0 = A + (size_t)ra0 * K + k0 + acc0c;
            const float* g1 = A + (size_t)ra1 * K + k0 + acc0c;
            uint32_t d0 = sA + (uint32_t)(buf * ASZ + arow0 * AST + acc0c) * 4u;
            uint32_t d1 = sA + (uint32_t)(buf * ASZ + arow1 * AST + acc0c) * 4u;
            asm volatile("cp.async.cg.shared.global [%0],[%1],16;\n" :: "r"(d0), "l"(g0));
            asm volatile("cp.async.cg.shared.global [%0],[%1],16;\n" :: "r"(d1), "l"(g1));
        }
        {
            int n0c = n0 + bcc0;
            int gcol = (n0c < N) ? n0c : (N - 4);
            int sz = (n0c < N) ? 16 : 0;
            const float* g0 = Bm + (size_t)(k0 + brow0) * N + gcol;
            const float* g1 = Bm + (size_t)(k0 + brow1) * N + gcol;
            uint32_t d0 = sB + (uint32_t)(buf * BSZ + brow0 * BST + bcc0) * 4u;
            uint32_t d1 = sB + (uint32_t)(buf * BSZ + brow1 * BST + bcc0) * 4u;
            asm volatile("cp.async.cg.shared.global [%0],[%1],16,%2;\n" :: "r"(d0), "l"(g0), "r"(sz));
            asm volatile("cp.async.cg.shared.global [%0],[%1],16,%2;\n" :: "r"(d1), "l"(g1), "r"(sz));
        }
    };

    auto docompute = [&](int buf) {
        const float* Ab = Asm + buf * ASZ;
        const float* Bb = Bsm + buf * BSZ;
#pragma unroll
        for (int kk = 0; kk < 2; kk++) {
            uint32_t af[4][4];
#pragma unroll
            for (int mi = 0; mi < 4; mi++) {
                int r = wm * 64 + mi * 16 + (lane >> 2);
                int c = kk * 8 + (lane & 3);
                af[mi][0] = __float_as_uint(Ab[r * AST + c]);
                af[mi][1] = __float_as_uint(Ab[(r + 8) * AST + c]);
                af[mi][2] = __float_as_uint(Ab[r * AST + c + 4]);
                af[mi][3] = __float_as_uint(Ab[(r + 8) * AST + c + 4]);
                if (RA) {
                    af[mi][0] = rna_tf32_u(af[mi][0]);
                    af[mi][1] = rna_tf32_u(af[mi][1]);
                    af[mi][2] = rna_tf32_u(af[mi][2]);
                    af[mi][3] = rna_tf32_u(af[mi][3]);
                }
            }
            uint32_t bf[4][2];
#pragma unroll
            for (int ni = 0; ni < 4; ni++) {
                int cc = wn * 32 + ni * 8 + (lane >> 2);
                int kb = kk * 8 + (lane & 3);
                bf[ni][0] = __float_as_uint(Bb[kb * BST + cc]);
                bf[ni][1] = __float_as_uint(Bb[(kb + 4) * BST + cc]);
                if (RB) {
                    bf[ni][0] = rna_tf32_u(bf[ni][0]);
                    bf[ni][1] = rna_tf32_u(bf[ni][1]);
                }
            }
#pragma unroll
            for (int mi = 0; mi < 4; mi++)
#pragma unroll
                for (int ni = 0; ni < 4; ni++) {
                    asm volatile(
                        "mma.sync.aligned.m16n8k8.row.col.f32.tf32.tf32.f32 "
                        "{%0,%1,%2,%3},{%4,%5,%6,%7},{%8,%9},{%0,%1,%2,%3};\n"
                        : "+f"(acc[mi][ni][0]), "+f"(acc[mi][ni][1]),
                          "+f"(acc[mi][ni][2]), "+f"(acc[mi][ni][3])
                        : "r"(af[mi][0]), "r"(af[mi][1]), "r"(af[mi][2]), "r"(af[mi][3]),
                          "r"(bf[ni][0]), "r"(bf[ni][1]));
                }
        }
    };

    issue(0, 0);
    asm volatile("cp.async.commit_group;\n");
    issue(1, 1);
    asm volatile("cp.async.commit_group;\n");

#pragma unroll 1
    for (int kt = 0; kt < KT; kt++) {
        if (kt + 1 < KT) {
            asm volatile("cp.async.wait_group 1;\n");
        } else {
            asm volatile("cp.async.wait_group 0;\n");
        }
        __syncthreads();
        if (kt + 2 < KT) {
            issue(kt + 2, (kt + 2) % 3);
            asm volatile("cp.async.commit_group;\n");
        }
        docompute(kt % 3);
    }

#pragma unroll
    for (int mi = 0; mi < 4; mi++) {
        int r = m0 + wm * 64 + mi * 16 + (lane >> 2);
#pragma unroll
        for (int ni = 0; ni < 4; ni++) {
            int c = n0 + wn * 32 + ni * 8 + (lane & 3) * 2;
            if (c < N && r < M) {
                float b0v = bias[c], b1v = bias[c + 1];
                float v0 = acc[mi][ni][0] + b0v;
                float v1 = acc[mi][ni][1] + b1v;
                float v2 = acc[mi][ni][2] + b0v;
                float v3 = acc[mi][ni][3] + b1v;
                if (RO) {
                    v0 = rna_tf32(v0); v1 = rna_tf32(v1);
                    v2 = rna_tf32(v2); v3 = rna_tf32(v3);
                }
                *reinterpret_cast<float2*>(&C[(size_t)r * N + c]) = make_float2(v0, v1);
                if (r + 8 < M)
                    *reinterpret_cast<float2*>(&C[(size_t)(r + 8) * N + c]) = make_float2(v2, v3);
            }
        }
    }
}

// ---------------- clustered bidirectional masked GRU scan ---------------------
// 4-CTA clusters; cluster = (batch-pair, dir); rank owns state dims [64r,64r+64)
// via a 192-column permuted-U slice held entirely in smem (192 KB, loaded once).
// Per step: smem matvec -> bar.cta -> gate update for own dims -> push h (dup
// u64) to all cluster CTAs via st.shared::cluster -> barrier.cluster (release/
// acquire orders the pushes). h parity-double-buffered so one cluster barrier
// per step suffices.
#define GRU_THREADS 192
#define GRU_SM_US   (UU * 192 * 4)               // 196608
#define GRU_SM_PART (4 * 2 * 192 * 4)            // 6144
#define GRU_SM_H    (2 * 2 * UU * 8)             // 8192
#define GRU_SMEM    (GRU_SM_US + GRU_SM_PART + GRU_SM_H)

__global__ void __launch_bounds__(GRU_THREADS, 1) __cluster_dims__(4, 1, 1)
gru_scan(const float* __restrict__ embW, const float* __restrict__ uperm,
         const float* __restrict__ bf1, const float* __restrict__ bb1,
         const int* __restrict__ tokens, float* __restrict__ hcat)
{
    extern __shared__ __align__(16) unsigned char smraw[];
    float* Us   = (float*)smraw;                                   // [256][192]
    float* part = (float*)(smraw + GRU_SM_US);                     // [4][2][192]
    unsigned long long* hbuf =
        (unsigned long long*)(smraw + GRU_SM_US + GRU_SM_PART);    // [2][2][256] (h,h)

    int tid  = threadIdx.x;
    int cid  = blockIdx.x >> 2;      // cluster id
    int rank = blockIdx.x & 3;       // rank within cluster
    int bp   = cid & 15;             // batch pair
    int dir  = cid >> 4;
    int b0   = bp * 2;

    const float* bv = dir ? bb1 : bf1;   // b[1] row (768)

    // prologue: U slice -> smem, h buffers -> 0
    {
        const float4* src = (const float4*)(uperm + (size_t)(dir * 4 + rank) * UU * 192);
        float4* dst = (float4*)Us;
        for (int i = tid; i < UU * 192 / 4; i += GRU_THREADS) dst[i] = src[i];
        for (int i = tid; i < 2 * 2 * UU; i += GRU_THREADS) hbuf[i] = 0ull;
    }
    __syncthreads();
    CLUSTER_ARRIVE();
    CLUSTER_WAIT();

    // matvec identity
    int kc = tid / 48;     // 0..3 (k-range of 64)
    int ct = tid % 48;     // 4 permuted cols each

    // update identity (tid < 128)
    int jj = tid & 63;
    int ub = tid >> 6;     // batch within pair
    int j  = rank * 64 + jj;
    float bz = 0.f, br = 0.f, bh = 0.f;
    if (tid < 128) { bz = bv[j]; br = bv[UU + j]; bh = bv[2 * UU + j]; }

    // precompute peer DSMEM addresses of hbuf base
    uint32_t hl = (uint32_t)__cvta_generic_to_shared(hbuf);
    uint32_t hpeer[4];
#pragma unroll
    for (int r = 0; r < 4; r++) hpeer[r] = mapa_u32(hl, r);

    const ulonglong2* U2 = (const ulonglong2*)Us;

    for (int i = 0; i < SS; i++) {
        int s = dir ? (SS - 1 - i) : i;
        int p = i & 1;
        size_t rb = (size_t)b0 * SS + s + (size_t)ub * SS;  // row for update thread

        // prefetch gate row + token for update phase (covered by matvec)
        float pz = 0.f, pr = 0.f, ph = 0.f; int tk = 1;
        if (tid < 128) {
            tk = tokens[rb];
            const float* xr = embW + (size_t)tk * H6 + dir * H3;
            pz = xr[j]; pr = xr[UU + j]; ph = xr[2 * UU + j];
        }

        // ---- smem matvec: partial inner over k-range [64kc, 64kc+64) ----
        {
            unsigned long long a00 = 0, a01 = 0, a10 = 0, a11 = 0;
            const ulonglong2* h0 = (const ulonglong2*)(hbuf + (p * 2 + 0) * UU) + kc * 32;
            const ulonglong2* h1 = (const ulonglong2*)(hbuf + (p * 2 + 1) * UU) + kc * 32;
            const ulonglong2* up = U2 + (size_t)(kc * 64) * 48 + ct;
#pragma unroll 4
            for (int kk = 0; kk < 32; kk++) {
                ulonglong2 uA = up[0];
                ulonglong2 uB = up[48];
                up += 96;
                ulonglong2 hA = h0[kk];
                ulonglong2 hB = h1[kk];
                FMA2(a00, uA.x, hA.x); FMA2(a01, uA.y, hA.x);
                FMA2(a10, uA.x, hB.x); FMA2(a11, uA.y, hB.x);
                FMA2(a00, uB.x, hA.y); FMA2(a01, uB.y, hA.y);
                FMA2(a10, uB.x, hB.y); FMA2(a11, uB.y, hB.y);
            }
            float2 p00 = unpack2(a00), p01 = unpack2(a01);
            float2 p10 = unpack2(a10), p11 = unpack2(a11);
            ((float4*)(part + (kc * 2 + 0) * 192))[ct] = make_float4(p00.x, p00.y, p01.x, p01.y);
            ((float4*)(part + (kc * 2 + 1) * 192))[ct] = make_float4(p10.x, p10.y, p11.x, p11.y);
        }
        __syncthreads();

        // ---- reduce partials + gate update for own 64 dims (tid < 128) ----
        if (tid < 128) {
            float iz = part[(0 + ub) * 192 + jj]       + part[(2 + ub) * 192 + jj]
                     + part[(4 + ub) * 192 + jj]       + part[(6 + ub) * 192 + jj];
            float ir = part[(0 + ub) * 192 + 64 + jj]  + part[(2 + ub) * 192 + 64 + jj]
                     + part[(4 + ub) * 192 + 64 + jj]  + part[(6 + ub) * 192 + 64 + jj];
            float ih = part[(0 + ub) * 192 + 128 + jj] + part[(2 + ub) * 192 + 128 + jj]
                     + part[(4 + ub) * 192 + 128 + jj] + part[(6 + ub) * 192 + 128 + jj];

            float hold = ((const float*)&hbuf[(p * 2 + ub) * UU + j])[0];
            float z = 1.f / (1.f + expf(-(pz + iz + bz)));
            float g = 1.f / (1.f + expf(-(pr + ir + br)));
            float c = tanhf(ph + g * (ih + bh));
            float hn = z * hold + (1.f - z) * c;
            if (tk == 0) hn = hold;

            unsigned long long hd = pack2(hn, hn);
            uint32_t off = (uint32_t)(((p ^ 1) * 2 + ub) * UU + j) * 8u;
#pragma unroll
            for (int r = 0; r < 4; r++)
                st_cluster_u64(hpeer[r] + off, hd);

            hcat[rb * (2 * UU) + dir * UU + j] = rna_tf32(hn);
        }
        // release own stores / acquire peers' stores for next step
        CLUSTER_ARRIVE();
        CLUSTER_WAIT();
    }
}

// ---------------- host launcher ----------------------------------------------
extern "C" void kernel_launch(void* const* d_in, const int* in_sizes, int n_in,
                              void* d_out, int out_size)
{
    const int*   tokens = (const int*)d_in[0];
    const float* emb    = (const float*)d_in[1];
    const float* W_f    = (const float*)d_in[2];
    const float* U_f    = (const float*)d_in[3];
    const float* b_f    = (const float*)d_in[4];
    const float* W_b    = (const float*)d_in[5];
    const float* U_b    = (const float*)d_in[6];
    const float* b_b    = (const float*)d_in[7];
    const float* W1     = (const float*)d_in[8];
    const float* b1     = (const float*)d_in[9];
    const float* W2     = (const float*)d_in[10];
    const float* b2     = (const float*)d_in[11];
    float* out = (float*)d_out;

    float *embw, *wcat, *bcat, *hcat, *wf, *bfv, *bpart, *zb, *uperm;
    cudaGetSymbolAddress((void**)&embw,  g_embw);
    cudaGetSymbolAddress((void**)&wcat,  g_wcat);
    cudaGetSymbolAddress((void**)&bcat,  g_bcat);
    cudaGetSymbolAddress((void**)&hcat,  g_hcat);
    cudaGetSymbolAddress((void**)&wf,    g_wf);
    cudaGetSymbolAddress((void**)&bfv,   g_bf);
    cudaGetSymbolAddress((void**)&bpart, g_bpart);
    cudaGetSymbolAddress((void**)&zb,    g_zb);
    cudaGetSymbolAddress((void**)&uperm, g_uperm);

    cudaFuncSetAttribute(gemm_tf32<1,1,0>, cudaFuncAttributeMaxDynamicSharedMemorySize, GEMM_SMEM);
    cudaFuncSetAttribute(gemm_tf32<1,1,1>, cudaFuncAttributeMaxDynamicSharedMemorySize, GEMM_SMEM);
    cudaFuncSetAttribute(gemm_tf32<0,0,0>, cudaFuncAttributeMaxDynamicSharedMemorySize, GEMM_SMEM);
    cudaFuncSetAttribute(gru_scan, cudaFuncAttributeMaxDynamicSharedMemorySize, GRU_SMEM);

    // 1) prep: weight concat + U permute
    build_wcat<<<(DD * H6 + 255) / 256, 256>>>(W_f, W_b, b_f, b_b, wcat, bcat);
    permute_u<<<(2 * 4 * UU * 192 + 255) / 256, 256>>>(U_f, U_b, uperm);

    // 2) embW = rna(emb) @ rna([W_f|W_b]) + [b_f0|b_b0]   [8000, 1536]
    {
        int nbx = H6 / BN;                       // 12
        int nby = (VV + BM - 1) / BM;            // 63
        gemm_tf32<1,1,0><<<nbx * nby, 256, GEMM_SMEM>>>(emb, wcat, bcat, embw, VV, H6, DD);
    }

    // 3) fused output weight: Wf = rna(W1) @ rna(W2), rounded output
    {
        int nbx = (VV + BN - 1) / BN;            // 63
        int nby = (2 * UU) / BM;                 // 4
        gemm_tf32<1,1,1><<<nbx * nby, 256, GEMM_SMEM>>>(W1, W2, zb, wf, 2 * UU, VV, VV);
    }
    // fused bias: bf = b1 @ W2 + b2 (exact fp32, K split 32 ways)
    bias_fuse_part<<<dim3((VV + 127) / 128, 32), 128>>>(b1, W2, bpart);
    bias_fuse_reduce<<<(VV + 127) / 128, 128>>>(bpart, b2, bfv);

    // 4) clustered bidirectional GRU scan (128 CTAs, 4-CTA clusters)
    gru_scan<<<128, GRU_THREADS, GRU_SMEM>>>(embw, uperm, b_f + H3, b_b + H3,
                                             tokens, hcat);

    // 5) logits = hcat @ Wf + bf -> output
    {
        int nbx = (VV + BN - 1) / BN, nby = MR / BM;  // 63 x 64
        gemm_tf32<0,0,0><<<nbx * nby, 256, GEMM_SMEM>>>(hcat, wf, bfv, out, MR, VV, 2 * UU);
    }
}

// round 8
// speedup vs baseline: 1.8055x; 1.0345x over previous
#include <cuda_runtime.h>
#include <cstdint>

#define VV 8000
#define DD 128
#define UU 256
#define BB 32
#define SS 256
#define H3 768
#define H6 1536
#define MR 8192   // B*S
#define SPLITK 4
#define KCHUNK (VV / SPLITK)   // 2000

// ---------------- scratch (static device allocations; no cudaMalloc) ---------
__device__ __align__(128) float g_embr[VV * DD];       // rna(emb)
__device__ __align__(128) float g_embw[VV * H6];       // emb proj + bias
__device__ __align__(128) float g_wcat[DD * H6];       // rna([W_f|W_b])
__device__ __align__(128) float g_bcat[H6];
__device__ __align__(128) float g_hcat[MR * 2 * UU];   // rna-rounded by GRU
__device__ __align__(128) float g_w1r[2 * UU * VV];    // rna(W1)
__device__ __align__(128) float g_w2r[VV * VV];        // rna(W2)
__device__ __align__(128) float g_wf[2 * UU * VV];     // rna(W1@W2) [512,8000]
__device__ __align__(128) float g_part[SPLITK * 2 * UU * VV];  // split-K partials
__device__ __align__(128) float g_bf[VV];
__device__ __align__(128) float g_bpart[32 * VV];
__device__ __align__(128) float g_zb[VV];              // zero bias (never written)
__device__ __align__(128) float g_uperm[2 * 4 * UU * 192];

__device__ __forceinline__ float rna_tf32(float x) {
    uint32_t u;
    asm("cvt.rna.tf32.f32 %0, %1;" : "=r"(u) : "f"(x));
    return __uint_as_float(u);
}

// packed f32x2 helpers (sm_103a)
__device__ __forceinline__ unsigned long long pack2(float x, float y) {
    unsigned long long r;
    asm("mov.b64 %0, {%1,%2};" : "=l"(r) : "f"(x), "f"(y));
    return r;
}
__device__ __forceinline__ float2 unpack2(unsigned long long v) {
    float2 r;
    asm("mov.b64 {%0,%1}, %2;" : "=f"(r.x), "=f"(r.y) : "l"(v));
    return r;
}
#define FMA2(acc, a, b) \
    asm("fma.rn.f32x2 %0, %1, %2, %0;" : "+l"(acc) : "l"(a), "l"(b))

// DSMEM / cluster helpers
__device__ __forceinline__ uint32_t mapa_u32(uint32_t laddr, uint32_t rank) {
    uint32_t r;
    asm("mapa.shared::cluster.u32 %0, %1, %2;" : "=r"(r) : "r"(laddr), "r"(rank));
    return r;
}
__device__ __forceinline__ void st_cluster_u64(uint32_t addr, unsigned long long v) {
    asm volatile("st.shared::cluster.u64 [%0], %1;" :: "r"(addr), "l"(v) : "memory");
}
#define CLUSTER_ARRIVE() asm volatile("barrier.cluster.arrive.aligned;" ::: "memory")
#define CLUSTER_WAIT()   asm volatile("barrier.cluster.wait.aligned;" ::: "memory")

// ---------------- small prep kernels ------------------------------------------
__global__ void cvt_rna4(const float4* __restrict__ in, float4* __restrict__ out, int n4) {
    int i = blockIdx.x * 256 + threadIdx.x;
    if (i < n4) {
        float4 v = in[i];
        v.x = rna_tf32(v.x); v.y = rna_tf32(v.y);
        v.z = rna_tf32(v.z); v.w = rna_tf32(v.w);
        out[i] = v;
    }
}

__global__ void splitk_reduce(const float4* __restrict__ p, float4* __restrict__ out, int n4) {
    int i = blockIdx.x * 256 + threadIdx.x;
    if (i >= n4) return;
    float4 a = p[i], b = p[i + n4], c = p[i + 2 * n4], d = p[i + 3 * n4];
    float4 r;
    r.x = rna_tf32(a.x + b.x + c.x + d.x);
    r.y = rna_tf32(a.y + b.y + c.y + d.y);
    r.z = rna_tf32(a.z + b.z + c.z + d.z);
    r.w = rna_tf32(a.w + b.w + c.w + d.w);
    out[i] = r;
}

__global__ void build_wcat(const float* __restrict__ Wf_, const float* __restrict__ Wb_,
                           const float* __restrict__ bf_, const float* __restrict__ bb_,
                           float* __restrict__ wcat, float* __restrict__ bcat) {
    int i = blockIdx.x * 256 + threadIdx.x;
    if (i < DD * H6) {
        int k = i / H6, j = i % H6;
        wcat[i] = rna_tf32((j < H3) ? Wf_[k * H3 + j] : Wb_[k * H3 + (j - H3)]);
    }
    if (i < H6)
        bcat[i] = (i < H3) ? bf_[i] : bb_[i - H3];
}

__global__ void permute_u(const float* __restrict__ Uf, const float* __restrict__ Ub,
                          float* __restrict__ uperm) {
    int idx = blockIdx.x * 256 + threadIdx.x;
    if (idx >= 2 * 4 * UU * 192) return;
    int c = idx % 192;
    int k = (idx / 192) % UU;
    int r = (idx / (192 * UU)) % 4;
    int dir = idx / (192 * UU * 4);
    const float* Um = dir ? Ub : Uf;
    int col = (c < 64) ? (64 * r + c)
            : (c < 128) ? (UU + 64 * r + (c - 64))
                        : (2 * UU + 64 * r + (c - 128));
    uperm[idx] = Um[k * H3 + col];
}

__global__ void bias_fuse_part(const float* __restrict__ b1v, const float* __restrict__ W2m,
                               float* __restrict__ part) {
    int n = blockIdx.x * 128 + threadIdx.x;
    if (n >= VV) return;
    int v0 = blockIdx.y * 250;
    float acc = 0.f;
#pragma unroll 5
    for (int v = v0; v < v0 + 250; v++)
        acc += b1v[v] * W2m[(size_t)v * VV + n];
    part[blockIdx.y * VV + n] = acc;
}
__global__ void bias_fuse_reduce(const float* __restrict__ part, const float* __restrict__ b2v,
                                 float* __restrict__ bf) {
    int n = blockIdx.x * 128 + threadIdx.x;
    if (n >= VV) return;
    float acc = b2v[n];
#pragma unroll
    for (int y = 0; y < 32; y++) acc += part[y * VV + n];
    bf[n] = acc;
}

// ---------------- tf32 GEMM (mma.sync, pre-rounded inputs) -------------------
// C[M,N] = A[M,K(chunk)] @ B[K,N] + bias[N]; 4-stage cp.async pipeline,
// one __syncthreads per k-tile. Split-K via blockIdx.y: A k-offset (row stride
// lda), B row block, C z-slice (czstride elements).
#define BM 128
#define BN 128
#define BKK 16
#define NST 4
#define AST 20
#define BST 136
#define ASZ (BM * AST)
#define BSZ (BKK * BST)
#define GEMM_SMEM (NST * (ASZ + BSZ) * 4)

__global__ void __launch_bounds__(256) gemm_tf32(
    const float* __restrict__ A, const float* __restrict__ Bm,
    const float* __restrict__ bias, float* __restrict__ C,
    int M, int N, int K, int lda, size_t czstride)
{
    extern __shared__ __align__(16) float sm[];
    float* Asm = sm;
    float* Bsm = sm + NST * ASZ;

    // split-K chunk offsets
    {
        int kz = blockIdx.y;
        A  += (size_t)kz * K;
        Bm += (size_t)kz * K * N;
        C  += (size_t)kz * czstride;
    }

    const int nbx = (N + BN - 1) / BN;
    const int nby = (M + BM - 1) / BM;
    const int CW = 16;
    int bid = blockIdx.x;
    int per = CW * nby;
    int chunk = bid / per;
    int rem = bid - chunk * per;
    int cw = min(CW, nbx - chunk * CW);
    int by = rem / cw;
    int bx = chunk * CW + (rem - by * cw);
    int m0 = by * BM, n0 = bx * BN;

    int tid = threadIdx.x;
    int lane = tid & 31;
    int wid = tid >> 5;
    int wm = wid >> 2;
    int wn = wid & 3;

    uint32_t sA = (uint32_t)__cvta_generic_to_shared(Asm);
    uint32_t sB = (uint32_t)__cvta_generic_to_shared(Bsm);

    int arow0 = tid >> 2;              int acc0c = (tid & 3) * 4;
    int arow1 = (tid + 256) >> 2;
    int brow0 = tid >> 5;              int bcc0 = (tid & 31) * 4;
    int brow1 = (tid + 256) >> 5;

    int ra0 = m0 + arow0; if (ra0 >= M) ra0 = M - 1;
    int ra1 = m0 + arow1; if (ra1 >= M) ra1 = M - 1;

    float acc[4][4][4];
#pragma unroll
    for (int a = 0; a < 4; a++)
#pragma unroll
        for (int b = 0; b < 4; b++)
#pragma unroll
            for (int c = 0; c < 4; c++) acc[a][b][c] = 0.f;

    const int KT = K / BKK;

    auto issue = [&](int kt, int buf) {
        int k0 = kt * BKK;
        {
            const float* g0 = A + (size_t)ra0 * lda + k0 + acc0c;
            const float* g1 = A + (size_t)ra1 * lda + k0 + acc0c;
            uint32_t d0 = sA + (uint32_t)(buf * ASZ + arow0 * AST + acc0c) * 4u;
            uint32_t d1 = sA + (uint32_t)(buf * ASZ + arow1 * AST + acc0c) * 4u;
            asm volatile("cp.async.cg.shared.global [%0],[%1],16;\n" :: "r"(d0), "l"(g0));
            asm volatile("cp.async.cg.shared.global [%0],[%1],16;\n" :: "r"(d1), "l"(g1));
        }
        {
            int n0c = n0 + bcc0;
            int gcol = (n0c < N) ? n0c : (N - 4);
            int sz = (n0c < N) ? 16 : 0;
            const float* g0 = Bm + (size_t)(k0 + brow0) * N + gcol;
            const float* g1 = Bm + (size_t)(k0 + brow1) * N + gcol;
            uint32_t d0 = sB + (uint32_t)(buf * BSZ + brow0 * BST + bcc0) * 4u;
            uint32_t d1 = sB + (uint32_t)(buf * BSZ + brow1 * BST + bcc0) * 4u;
            asm volatile("cp.async.cg.shared.global [%0],[%1],16,%2;\n" :: "r"(d0), "l"(g0), "r"(sz));
            asm volatile("cp.async.cg.shared.global [%0],[%1],16,%2;\n" :: "r"(d1), "l"(g1), "r"(sz));
        }
        asm volatile("cp.async.commit_group;\n");
    };

    auto docompute = [&](int buf) {
        const float* Ab = Asm + buf * ASZ;
        const float* Bb = Bsm + buf * BSZ;
#pragma unroll
        for (int kk = 0; kk < 2; kk++) {
            uint32_t af[4][4];
#pragma unroll
            for (int mi = 0; mi < 4; mi++) {
                int r = wm * 64 + mi * 16 + (lane >> 2);
                int c = kk * 8 + (lane & 3);
                af[mi][0] = __float_as_uint(Ab[r * AST + c]);
                af[mi][1] = __float_as_uint(Ab[(r + 8) * AST + c]);
                af[mi][2] = __float_as_uint(Ab[r * AST + c + 4]);
                af[mi][3] = __float_as_uint(Ab[(r + 8) * AST + c + 4]);
            }
            uint32_t bf[4][2];
#pragma unroll
            for (int ni = 0; ni < 4; ni++) {
                int cc = wn * 32 + ni * 8 + (lane >> 2);
                int kb = kk * 8 + (lane & 3);
                bf[ni][0] = __float_as_uint(Bb[kb * BST + cc]);
                bf[ni][1] = __float_as_uint(Bb[(kb + 4) * BST + cc]);
            }
#pragma unroll
            for (int mi = 0; mi < 4; mi++)
#pragma unroll
                for (int ni = 0; ni < 4; ni++) {
                    asm volatile(
                        "mma.sync.aligned.m16n8k8.row.col.f32.tf32.tf32.f32 "
                        "{%0,%1,%2,%3},{%4,%5,%6,%7},{%8,%9},{%0,%1,%2,%3};\n"
                        : "+f"(acc[mi][ni][0]), "+f"(acc[mi][ni][1]),
                          "+f"(acc[mi][ni][2]), "+f"(acc[mi][ni][3])
                        : "r"(af[mi][0]), "r"(af[mi][1]), "r"(af[mi][2]), "r"(af[mi][3]),
                          "r"(bf[ni][0]), "r"(bf[ni][1]));
                }
        }
    };

    // prologue: NST-1 stages in flight
    issue(0, 0);
    issue(1, 1);
    issue(2, 2);

#pragma unroll 1
    for (int kt = 0; kt < KT; kt++) {
        if (kt + 1 < KT) {
            asm volatile("cp.async.wait_group %0;\n" :: "n"(NST - 2));
        } else {
            asm volatile("cp.async.wait_group 0;\n");
        }
        __syncthreads();
        if (kt + NST - 1 < KT)
            issue(kt + NST - 1, (kt + NST - 1) & (NST - 1));
        docompute(kt & (NST - 1));
    }

    // epilogue
#pragma unroll
    for (int mi = 0; mi < 4; mi++) {
        int r = m0 + wm * 64 + mi * 16 + (lane >> 2);
#pragma unroll
        for (int ni = 0; ni < 4; ni++) {
            int c = n0 + wn * 32 + ni * 8 + (lane & 3) * 2;
            if (c < N && r < M) {
                float b0v = bias[c], b1v = bias[c + 1];
                float v0 = acc[mi][ni][0] + b0v;
                float v1 = acc[mi][ni][1] + b1v;
                float v2 = acc[mi][ni][2] + b0v;
                float v3 = acc[mi][ni][3] + b1v;
                *reinterpret_cast<float2*>(&C[(size_t)r * N + c]) = make_float2(v0, v1);
                if (r + 8 < M)
                    *reinterpret_cast<float2*>(&C[(size_t)(r + 8) * N + c]) = make_float2(v2, v3);
            }
        }
    }
}

// ---------------- clustered bidirectional masked GRU scan (R6, unchanged) -----
#define GRU_THREADS 192
#define GRU_SM_US   (UU * 192 * 4)
#define GRU_SM_PART (4 * 2 * 192 * 4)
#define GRU_SM_H    (2 * 2 * UU * 8)
#define GRU_SMEM    (GRU_SM_US + GRU_SM_PART + GRU_SM_H)

__global__ void __launch_bounds__(GRU_THREADS, 1) __cluster_dims__(4, 1, 1)
gru_scan(const float* __restrict__ embW, const float* __restrict__ uperm,
         const float* __restrict__ bf1, const float* __restrict__ bb1,
         const int* __restrict__ tokens, float* __restrict__ hcat)
{
    extern __shared__ __align__(16) unsigned char smraw[];
    float* Us   = (float*)smraw;
    float* part = (float*)(smraw + GRU_SM_US);
    unsigned long long* hbuf =
        (unsigned long long*)(smraw + GRU_SM_US + GRU_SM_PART);

    int tid  = threadIdx.x;
    int cid  = blockIdx.x >> 2;
    int rank = blockIdx.x & 3;
    int bp   = cid & 15;
    int dir  = cid >> 4;
    int b0   = bp * 2;

    const float* bv = dir ? bb1 : bf1;

    {
        const float4* src = (const float4*)(uperm + (size_t)(dir * 4 + rank) * UU * 192);
        float4* dst = (float4*)Us;
        for (int i = tid; i < UU * 192 / 4; i += GRU_THREADS) dst[i] = src[i];
        for (int i = tid; i < 2 * 2 * UU; i += GRU_THREADS) hbuf[i] = 0ull;
    }
    __syncthreads();
    CLUSTER_ARRIVE();
    CLUSTER_WAIT();

    int kc = tid / 48;
    int ct = tid % 48;

    int jj = tid & 63;
    int ub = tid >> 6;
    int j  = rank * 64 + jj;
    float bz = 0.f, br = 0.f, bh = 0.f;
    if (tid < 128) { bz = bv[j]; br = bv[UU + j]; bh = bv[2 * UU + j]; }

    uint32_t hl = (uint32_t)__cvta_generic_to_shared(hbuf);
    uint32_t hpeer[4];
#pragma unroll
    for (int r = 0; r < 4; r++) hpeer[r] = mapa_u32(hl, r);

    const ulonglong2* U2 = (const ulonglong2*)Us;

    for (int i = 0; i < SS; i++) {
        int s = dir ? (SS - 1 - i) : i;
        int p = i & 1;
        size_t rb = (size_t)b0 * SS + s + (size_t)ub * SS;

        float pz = 0.f, pr = 0.f, ph = 0.f; int tk = 1;
        if (tid < 128) {
            tk = tokens[rb];
            const float* xr = embW + (size_t)tk * H6 + dir * H3;
            pz = xr[j]; pr = xr[UU + j]; ph = xr[2 * UU + j];
        }

        {
            unsigned long long a00 = 0, a01 = 0, a10 = 0, a11 = 0;
            const ulonglong2* h0 = (const ulonglong2*)(hbuf + (p * 2 + 0) * UU) + kc * 32;
            const ulonglong2* h1 = (const ulonglong2*)(hbuf + (p * 2 + 1) * UU) + kc * 32;
            const ulonglong2* up = U2 + (size_t)(kc * 64) * 48 + ct;
#pragma unroll 4
            for (int kk = 0; kk < 32; kk++) {
                ulonglong2 uA = up[0];
                ulonglong2 uB = up[48];
                up += 96;
                ulonglong2 hA = h0[kk];
                ulonglong2 hB = h1[kk];
                FMA2(a00, uA.x, hA.x); FMA2(a01, uA.y, hA.x);
                FMA2(a10, uA.x, hB.x); FMA2(a11, uA.y, hB.x);
                FMA2(a00, uB.x, hA.y); FMA2(a01, uB.y, hA.y);
                FMA2(a10, uB.x, hB.y); FMA2(a11, uB.y, hB.y);
            }
            float2 p00 = unpack2(a00), p01 = unpack2(a01);
            float2 p10 = unpack2(a10), p11 = unpack2(a11);
            ((float4*)(part + (kc * 2 + 0) * 192))[ct] = make_float4(p00.x, p00.y, p01.x, p01.y);
            ((float4*)(part + (kc * 2 + 1) * 192))[ct] = make_float4(p10.x, p10.y, p11.x, p11.y);
        }
        __syncthreads();

        if (tid < 128) {
            float iz = part[(0 + ub) * 192 + jj]       + part[(2 + ub) * 192 + jj]
                     + part[(4 + ub) * 192 + jj]       + part[(6 + ub) * 192 + jj];
            float ir = part[(0 + ub) * 192 + 64 + jj]  + part[(2 + ub) * 192 + 64 + jj]
                     + part[(4 + ub) * 192 + 64 + jj]  + part[(6 + ub) * 192 + 64 + jj];
            float ih = part[(0 + ub) * 192 + 128 + jj] + part[(2 + ub) * 192 + 128 + jj]
                     + part[(4 + ub) * 192 + 128 + jj] + part[(6 + ub) * 192 + 128 + jj];

            float hold = ((const float*)&hbuf[(p * 2 + ub) * UU + j])[0];
            float z = 1.f / (1.f + expf(-(pz + iz + bz)));
            float g = 1.f / (1.f + expf(-(pr + ir + br)));
            float c = tanhf(ph + g * (ih + bh));
            float hn = z * hold + (1.f - z) * c;
            if (tk == 0) hn = hold;

            unsigned long long hd = pack2(hn, hn);
            uint32_t off = (uint32_t)(((p ^ 1) * 2 + ub) * UU + j) * 8u;
#pragma unroll
            for (int r = 0; r < 4; r++)
                st_cluster_u64(hpeer[r] + off, hd);

            hcat[rb * (2 * UU) + dir * UU + j] = rna_tf32(hn);
        }
        CLUSTER_ARRIVE();
        CLUSTER_WAIT();
    }
}

// ---------------- host launcher ----------------------------------------------
extern "C" void kernel_launch(void* const* d_in, const int* in_sizes, int n_in,
                              void* d_out, int out_size)
{
    const int*   tokens = (const int*)d_in[0];
    const float* emb    = (const float*)d_in[1];
    const float* W_f    = (const float*)d_in[2];
    const float* U_f    = (const float*)d_in[3];
    const float* b_f    = (const float*)d_in[4];
    const float* W_b    = (const float*)d_in[5];
    const float* U_b    = (const float*)d_in[6];
    const float* b_b    = (const float*)d_in[7];
    const float* W1     = (const float*)d_in[8];
    const float* b1     = (const float*)d_in[9];
    const float* W2     = (const float*)d_in[10];
    const float* b2     = (const float*)d_in[11];
    float* out = (float*)d_out;

    float *embr, *embw, *wcat, *bcat, *hcat, *w1r, *w2r, *wf, *partk, *bfv, *bpart, *zb, *uperm;
    cudaGetSymbolAddress((void**)&embr,  g_embr);
    cudaGetSymbolAddress((void**)&embw,  g_embw);
    cudaGetSymbolAddress((void**)&wcat,  g_wcat);
    cudaGetSymbolAddress((void**)&bcat,  g_bcat);
    cudaGetSymbolAddress((void**)&hcat,  g_hcat);
    cudaGetSymbolAddress((void**)&w1r,   g_w1r);
    cudaGetSymbolAddress((void**)&w2r,   g_w2r);
    cudaGetSymbolAddress((void**)&wf,    g_wf);
    cudaGetSymbolAddress((void**)&partk, g_part);
    cudaGetSymbolAddress((void**)&bfv,   g_bf);
    cudaGetSymbolAddress((void**)&bpart, g_bpart);
    cudaGetSymbolAddress((void**)&zb,    g_zb);
    cudaGetSymbolAddress((void**)&uperm, g_uperm);

    cudaFuncSetAttribute(gemm_tf32, cudaFuncAttributeMaxDynamicSharedMemorySize, GEMM_SMEM);
    cudaFuncSetAttribute(gru_scan,  cudaFuncAttributeMaxDynamicSharedMemorySize, GRU_SMEM);

    // 1) prep: rna-round all GEMM inputs once; concat; permute U
    cvt_rna4<<<(2 * UU * VV / 4 + 255) / 256, 256>>>((const float4*)W1, (float4*)w1r, 2 * UU * VV / 4);
    cvt_rna4<<<(VV * VV / 4 + 255) / 256, 256>>>((const float4*)W2, (float4*)w2r, VV * VV / 4);
    cvt_rna4<<<(VV * DD / 4 + 255) / 256, 256>>>((const float4*)emb, (float4*)embr, VV * DD / 4);
    build_wcat<<<(DD * H6 + 255) / 256, 256>>>(W_f, W_b, b_f, b_b, wcat, bcat);
    permute_u<<<(2 * 4 * UU * 192 + 255) / 256, 256>>>(U_f, U_b, uperm);

    // 2) Wf = rna(W1) @ rna(W2), split-K x4 (fp32 partials) + reduce/rna
    {
        int nbx = (VV + BN - 1) / BN;            // 63
        int nby = (2 * UU + BM - 1) / BM;        // 4
        gemm_tf32<<<dim3(nbx * nby, SPLITK), 256, GEMM_SMEM>>>(
            w1r, w2r, zb, partk, 2 * UU, VV, KCHUNK, VV, (size_t)2 * UU * VV);
        splitk_reduce<<<(2 * UU * VV / 4 + 255) / 256, 256>>>(
            (const float4*)partk, (float4*)wf, 2 * UU * VV / 4);
    }
    // fused bias: bf = b1 @ W2 + b2 (exact fp32, K split 32 ways)
    bias_fuse_part<<<dim3((VV + 127) / 128, 32), 128>>>(b1, W2, bpart);
    bias_fuse_reduce<<<(VV + 127) / 128, 128>>>(bpart, b2, bfv);

    // 3) embW = rna(emb) @ rna([W_f|W_b]) + [b_f0|b_b0]   [8000, 1536]
    {
        int nbx = H6 / BN;                       // 12
        int nby = (VV + BM - 1) / BM;            // 63
        gemm_tf32<<<dim3(nbx * nby, 1), 256, GEMM_SMEM>>>(
            embr, wcat, bcat, embw, VV, H6, DD, DD, 0);
    }

    // 4) clustered bidirectional GRU scan
    gru_scan<<<128, GRU_THREADS, GRU_SMEM>>>(embw, uperm, b_f + H3, b_b + H3,
                                             tokens, hcat);

    // 5) logits = hcat @ Wf + bf -> output
    {
        int nbx = (VV + BN - 1) / BN;            // 63
        int nby = MR / BM;                       // 64
        gemm_tf32<<<dim3(nbx * nby, 1), 256, GEMM_SMEM>>>(
            hcat, wf, bfv, out, MR, VV, 2 * UU, 2 * UU, 0);
    }
}

// round 9
// speedup vs baseline: 2.3017x; 1.2749x over previous
#include <cuda_runtime.h>
#include <cuda_fp16.h>
#include <cstdint>

#define VV 8000
#define DD 128
#define UU 256
#define BB 32
#define SS 256
#define H3 768
#define H6 1536
#define MR 8192   // B*S

// ---------------- scratch (static device allocations; no cudaMalloc) ---------
__device__ __align__(128) __half g_w1h[2 * UU * VV];    // fp16(W1) [512,8000]
__device__ __align__(128) __half g_w2t[VV * VV];        // fp16(W2^T) [8000,8000]
__device__ __align__(128) __half g_embh[VV * DD];       // fp16(emb)
__device__ __align__(128) __half g_wcatt[H6 * DD];      // fp16([W_f|W_b]^T) [1536,128]
__device__ __align__(128) float  g_bcat[H6];
__device__ __align__(128) float  g_embw[VV * H6];       // emb proj + bias (fp32)
__device__ __align__(128) __half g_hcat[MR * 2 * UU];   // fp16 GRU outputs
__device__ __align__(128) __half g_wfth[VV * 2 * UU];   // fp16((W1@W2)^T) [8000,512]
__device__ __align__(128) float  g_bf[VV];
__device__ __align__(128) float  g_bpart[32 * VV];
__device__ __align__(128) float  g_uperm[2 * 4 * UU * 192];

// packed f32x2 helpers (sm_103a)
__device__ __forceinline__ unsigned long long pack2(float x, float y) {
    unsigned long long r;
    asm("mov.b64 %0, {%1,%2};" : "=l"(r) : "f"(x), "f"(y));
    return r;
}
__device__ __forceinline__ float2 unpack2(unsigned long long v) {
    float2 r;
    asm("mov.b64 {%0,%1}, %2;" : "=f"(r.x), "=f"(r.y) : "l"(v));
    return r;
}
#define FMA2(acc, a, b) \
    asm("fma.rn.f32x2 %0, %1, %2, %0;" : "+l"(acc) : "l"(a), "l"(b))

// DSMEM / cluster helpers
__device__ __forceinline__ uint32_t mapa_u32(uint32_t laddr, uint32_t rank) {
    uint32_t r;
    asm("mapa.shared::cluster.u32 %0, %1, %2;" : "=r"(r) : "r"(laddr), "r"(rank));
    return r;
}
__device__ __forceinline__ void st_cluster_u64(uint32_t addr, unsigned long long v) {
    asm volatile("st.shared::cluster.u64 [%0], %1;" :: "r"(addr), "l"(v) : "memory");
}
#define CLUSTER_ARRIVE() asm volatile("barrier.cluster.arrive.aligned;" ::: "memory")
#define CLUSTER_WAIT()   asm volatile("barrier.cluster.wait.aligned;" ::: "memory")

// ---------------- prep kernels -------------------------------------------------
__global__ void cvt_f16(const float4* __restrict__ in, uint2* __restrict__ out, int n4) {
    int i = blockIdx.x * 256 + threadIdx.x;
    if (i < n4) {
        float4 v = in[i];
        __half2 h0 = __floats2half2_rn(v.x, v.y);
        __half2 h1 = __floats2half2_rn(v.z, v.w);
        uint2 r;
        r.x = *reinterpret_cast<uint32_t*>(&h0);
        r.y = *reinterpret_cast<uint32_t*>(&h1);
        out[i] = r;
    }
}

// W2 [8000,8000] fp32 -> fp16(W2^T)
__global__ void transpose_f16(const float* __restrict__ in, __half* __restrict__ out) {
    __shared__ float t[32][33];
    int bx = blockIdx.x * 32;   // col base (of in)
    int by = blockIdx.y * 32;   // row base (of in)
    int x = threadIdx.x, y0 = threadIdx.y;
#pragma unroll
    for (int dy = 0; dy < 32; dy += 8)
        t[y0 + dy][x] = in[(size_t)(by + y0 + dy) * VV + bx + x];
    __syncthreads();
#pragma unroll
    for (int dy = 0; dy < 32; dy += 8)
        out[(size_t)(bx + y0 + dy) * VV + by + x] = __float2half_rn(t[x][y0 + dy]);
}

// [W_f|W_b]^T as fp16 [1536 n][128 k] + bias concat
__global__ void build_wcat(const float* __restrict__ Wf_, const float* __restrict__ Wb_,
                           const float* __restrict__ bf_, const float* __restrict__ bb_,
                           __half* __restrict__ wcatt, float* __restrict__ bcat) {
    int i = blockIdx.x * 256 + threadIdx.x;
    if (i < H6 * DD) {
        int n = i / DD, k = i % DD;
        float v = (n < H3) ? Wf_[k * H3 + n] : Wb_[k * H3 + (n - H3)];
        wcatt[i] = __float2half_rn(v);
    }
    if (i < H6)
        bcat[i] = (i < H3) ? bf_[i] : bb_[i - H3];
}

__global__ void permute_u(const float* __restrict__ Uf, const float* __restrict__ Ub,
                          float* __restrict__ uperm) {
    int idx = blockIdx.x * 256 + threadIdx.x;
    if (idx >= 2 * 4 * UU * 192) return;
    int c = idx % 192;
    int k = (idx / 192) % UU;
    int r = (idx / (192 * UU)) % 4;
    int dir = idx / (192 * UU * 4);
    const float* Um = dir ? Ub : Uf;
    int col = (c < 64) ? (64 * r + c)
            : (c < 128) ? (UU + 64 * r + (c - 64))
                        : (2 * UU + 64 * r + (c - 128));
    uperm[idx] = Um[k * H3 + col];
}

__global__ void bias_fuse_part(const float* __restrict__ b1v, const float* __restrict__ W2m,
                               float* __restrict__ part) {
    int n = blockIdx.x * 128 + threadIdx.x;
    if (n >= VV) return;
    int v0 = blockIdx.y * 250;
    float acc = 0.f;
#pragma unroll 5
    for (int v = v0; v < v0 + 250; v++)
        acc += b1v[v] * W2m[(size_t)v * VV + n];
    part[blockIdx.y * VV + n] = acc;
}
__global__ void bias_fuse_reduce(const float* __restrict__ part, const float* __restrict__ b2v,
                                 float* __restrict__ bf) {
    int n = blockIdx.x * 128 + threadIdx.x;
    if (n >= VV) return;
    float acc = b2v[n];
#pragma unroll
    for (int y = 0; y < 32; y++) acc += part[y * VV + n];
    bf[n] = acc;
}

// ---------------- fp16 GEMM (mma.sync m16n8k16, fp32 accum) -------------------
// C[M,N] = A[M,K] @ B where B given n-major: Bt[n][k]. CTA tile 128x256,
// warp tile 64x64, k-tile 32, 4-stage cp.async. OUTF16=1: fp16 C, no bias.
#define HBM_ 128
#define HBN_ 256
#define HBK_ 32
#define HNST 4
#define HROWB 80                      // smem row stride bytes (40 halfs)
#define HASB (HBM_ * HROWB)           // 10240
#define HBSB (HBN_ * HROWB)           // 20480
#define HSTG (HASB + HBSB)            // 30720
#define HGE_SMEM (HNST * HSTG)        // 122880

template <int OUTF16>
__global__ void __launch_bounds__(256) gemm_h(
    const __half* __restrict__ A, const __half* __restrict__ Bt,
    const float* __restrict__ bias, void* __restrict__ Cv,
    int M, int N, int K)
{
    extern __shared__ __align__(16) unsigned char sm[];

    int ntiles = (N + HBN_ - 1) / HBN_;
    int mt = blockIdx.x / ntiles, nt = blockIdx.x % ntiles;
    int m0 = mt * HBM_, n0 = nt * HBN_;

    int tid = threadIdx.x;
    int lane = tid & 31;
    int wid = tid >> 5;
    int wm = wid >> 2;   // 0..1
    int wn = wid & 3;    // 0..3
    int g = lane >> 2;   // 0..7
    int t4 = lane & 3;   // 0..3

    uint32_t sbase = (uint32_t)__cvta_generic_to_shared(sm);

    float acc[4][8][4];
#pragma unroll
    for (int a = 0; a < 4; a++)
#pragma unroll
        for (int b = 0; b < 8; b++)
#pragma unroll
            for (int c = 0; c < 4; c++) acc[a][b][c] = 0.f;

    const int KT = K / HBK_;

    auto issue = [&](int kt, int slot) {
        int k0 = kt * HBK_;
        uint32_t ab = sbase + slot * HSTG;
        uint32_t bb = ab + HASB;
#pragma unroll
        for (int i = 0; i < 2; i++) {          // A: 128 rows x 4 16B-chunks
            int ch = tid + i * 256;
            int r = ch >> 2, c16 = ch & 3;
            int ra = m0 + r; if (ra >= M) ra = M - 1;
            const __half* src = A + (size_t)ra * K + k0 + c16 * 8;
            uint32_t dst = ab + (uint32_t)(r * HROWB + c16 * 16);
            asm volatile("cp.async.cg.shared.global [%0],[%1],16;\n" :: "r"(dst), "l"(src));
        }
#pragma unroll
        for (int i = 0; i < 4; i++) {          // B: 256 rows x 4 chunks
            int ch = tid + i * 256;
            int r = ch >> 2, c16 = ch & 3;
            int nb = n0 + r;
            int sz = (nb < N) ? 16 : 0;
            if (nb >= N) nb = N - 1;
            const __half* src = Bt + (size_t)nb * K + k0 + c16 * 8;
            uint32_t dst = bb + (uint32_t)(r * HROWB + c16 * 16);
            asm volatile("cp.async.cg.shared.global [%0],[%1],16,%2;\n" :: "r"(dst), "l"(src), "r"(sz));
        }
        asm volatile("cp.async.commit_group;\n");
    };

    auto docompute = [&](int slot) {
        const unsigned char* As = sm + slot * HSTG;
        const unsigned char* Bs = As + HASB;
#pragma unroll
        for (int kk = 0; kk < 2; kk++) {
            int kb = kk * 32 + t4 * 4;         // byte offset of (k = 16kk + 2t)
            uint32_t af[4][4];
#pragma unroll
            for (int mi = 0; mi < 4; mi++) {
                int row = wm * 64 + mi * 16 + g;
                const unsigned char* p = As + row * HROWB + kb;
                af[mi][0] = *(const uint32_t*)(p);
                af[mi][1] = *(const uint32_t*)(p + 8 * HROWB);
                af[mi][2] = *(const uint32_t*)(p + 16);
                af[mi][3] = *(const uint32_t*)(p + 8 * HROWB + 16);
            }
            uint32_t bf[8][2];
#pragma unroll
            for (int ni = 0; ni < 8; ni++) {
                int nr = wn * 64 + ni * 8 + g;
                const unsigned char* p = Bs + nr * HROWB + kb;
                bf[ni][0] = *(const uint32_t*)(p);
                bf[ni][1] = *(const uint32_t*)(p + 16);
            }
#pragma unroll
            for (int mi = 0; mi < 4; mi++)
#pragma unroll
                for (int ni = 0; ni < 8; ni++) {
                    asm volatile(
                        "mma.sync.aligned.m16n8k16.row.col.f32.f16.f16.f32 "
                        "{%0,%1,%2,%3},{%4,%5,%6,%7},{%8,%9},{%0,%1,%2,%3};\n"
                        : "+f"(acc[mi][ni][0]), "+f"(acc[mi][ni][1]),
                          "+f"(acc[mi][ni][2]), "+f"(acc[mi][ni][3])
                        : "r"(af[mi][0]), "r"(af[mi][1]), "r"(af[mi][2]), "r"(af[mi][3]),
                          "r"(bf[ni][0]), "r"(bf[ni][1]));
                }
        }
    };

    // prologue: 3 stages in flight
    issue(0, 0);
    if (KT > 1) issue(1, 1);
    if (KT > 2) issue(2, 2);

#pragma unroll 1
    for (int kt = 0; kt < KT; kt++) {
        if (kt + 1 < KT) {
            asm volatile("cp.async.wait_group %0;\n" :: "n"(HNST - 2));
        } else {
            asm volatile("cp.async.wait_group 0;\n");
        }
        __syncthreads();
        if (kt + HNST - 1 < KT)
            issue(kt + HNST - 1, (kt + HNST - 1) & (HNST - 1));
        docompute(kt & (HNST - 1));
    }

    // epilogue
#pragma unroll
    for (int ni = 0; ni < 8; ni++) {
        int c = n0 + wn * 64 + ni * 8 + t4 * 2;
        if (c >= N) continue;
        float b0v = 0.f, b1v = 0.f;
        if (!OUTF16) { b0v = bias[c]; b1v = bias[c + 1]; }
#pragma unroll
        for (int mi = 0; mi < 4; mi++) {
            int r = m0 + wm * 64 + mi * 16 + g;
            if (r >= M) continue;
            if (OUTF16) {
                __half* C = (__half*)Cv;
                __half2 h0 = __floats2half2_rn(acc[mi][ni][0], acc[mi][ni][1]);
                *reinterpret_cast<__half2*>(&C[(size_t)r * N + c]) = h0;
                if (r + 8 < M) {
                    __half2 h1 = __floats2half2_rn(acc[mi][ni][2], acc[mi][ni][3]);
                    *reinterpret_cast<__half2*>(&C[(size_t)(r + 8) * N + c]) = h1;
                }
            } else {
                float* C = (float*)Cv;
                *reinterpret_cast<float2*>(&C[(size_t)r * N + c]) =
                    make_float2(acc[mi][ni][0] + b0v, acc[mi][ni][1] + b1v);
                if (r + 8 < M)
                    *reinterpret_cast<float2*>(&C[(size_t)(r + 8) * N + c]) =
                        make_float2(acc[mi][ni][2] + b0v, acc[mi][ni][3] + b1v);
            }
        }
    }
}

// ---------------- clustered bidirectional masked GRU scan ---------------------
#define GRU_THREADS 192
#define GRU_SM_US   (UU * 192 * 4)
#define GRU_SM_PART (4 * 2 * 192 * 4)
#define GRU_SM_H    (2 * 2 * UU * 8)
#define GRU_SMEM    (GRU_SM_US + GRU_SM_PART + GRU_SM_H)

__global__ void __launch_bounds__(GRU_THREADS, 1) __cluster_dims__(4, 1, 1)
gru_scan(const float* __restrict__ embW, const float* __restrict__ uperm,
         const float* __restrict__ bf1, const float* __restrict__ bb1,
         const int* __restrict__ tokens, __half* __restrict__ hcat)
{
    extern __shared__ __align__(16) unsigned char smraw[];
    float* Us   = (float*)smraw;
    float* part = (float*)(smraw + GRU_SM_US);
    unsigned long long* hbuf =
        (unsigned long long*)(smraw + GRU_SM_US + GRU_SM_PART);

    int tid  = threadIdx.x;
    int cid  = blockIdx.x >> 2;
    int rank = blockIdx.x & 3;
    int bp   = cid & 15;
    int dir  = cid >> 4;
    int b0   = bp * 2;

    const float* bv = dir ? bb1 : bf1;

    {
        const float4* src = (const float4*)(uperm + (size_t)(dir * 4 + rank) * UU * 192);
        float4* dst = (float4*)Us;
        for (int i = tid; i < UU * 192 / 4; i += GRU_THREADS) dst[i] = src[i];
        for (int i = tid; i < 2 * 2 * UU; i += GRU_THREADS) hbuf[i] = 0ull;
    }
    __syncthreads();
    CLUSTER_ARRIVE();
    CLUSTER_WAIT();

    int kc = tid / 48;
    int ct = tid % 48;

    int jj = tid & 63;
    int ub = tid >> 6;
    int j  = rank * 64 + jj;
    float bz = 0.f, br = 0.f, bh = 0.f;
    if (tid < 128) { bz = bv[j]; br = bv[UU + j]; bh = bv[2 * UU + j]; }

    uint32_t hl = (uint32_t)__cvta_generic_to_shared(hbuf);
    uint32_t hpeer[4];
#pragma unroll
    for (int r = 0; r < 4; r++) hpeer[r] = mapa_u32(hl, r);

    const ulonglong2* U2 = (const ulonglong2*)Us;

    for (int i = 0; i < SS; i++) {
        int s = dir ? (SS - 1 - i) : i;
        int p = i & 1;
        size_t rb = (size_t)b0 * SS + s + (size_t)ub * SS;

        float pz = 0.f, pr = 0.f, ph = 0.f; int tk = 1;
        if (tid < 128) {
            tk = tokens[rb];
            const float* xr = embW + (size_t)tk * H6 + dir * H3;
            pz = xr[j]; pr = xr[UU + j]; ph = xr[2 * UU + j];
        }

        {
            unsigned long long a00 = 0, a01 = 0, a10 = 0, a11 = 0;
            const ulonglong2* h0 = (const ulonglong2*)(hbuf + (p * 2 + 0) * UU) + kc * 32;
            const ulonglong2* h1 = (const ulonglong2*)(hbuf + (p * 2 + 1) * UU) + kc * 32;
            const ulonglong2* up = U2 + (size_t)(kc * 64) * 48 + ct;
#pragma unroll 4
            for (int kk = 0; kk < 32; kk++) {
                ulonglong2 uA = up[0];
                ulonglong2 uB = up[48];
                up += 96;
                ulonglong2 hA = h0[kk];
                ulonglong2 hB = h1[kk];
                FMA2(a00, uA.x, hA.x); FMA2(a01, uA.y, hA.x);
                FMA2(a10, uA.x, hB.x); FMA2(a11, uA.y, hB.x);
                FMA2(a00, uB.x, hA.y); FMA2(a01, uB.y, hA.y);
                FMA2(a10, uB.x, hB.y); FMA2(a11, uB.y, hB.y);
            }
            float2 p00 = unpack2(a00), p01 = unpack2(a01);
            float2 p10 = unpack2(a10), p11 = unpack2(a11);
            ((float4*)(part + (kc * 2 + 0) * 192))[ct] = make_float4(p00.x, p00.y, p01.x, p01.y);
            ((float4*)(part + (kc * 2 + 1) * 192))[ct] = make_float4(p10.x, p10.y, p11.x, p11.y);
        }
        __syncthreads();

        if (tid < 128) {
            float iz = part[(0 + ub) * 192 + jj]       + part[(2 + ub) * 192 + jj]
                     + part[(4 + ub) * 192 + jj]       + part[(6 + ub) * 192 + jj];
            float ir = part[(0 + ub) * 192 + 64 + jj]  + part[(2 + ub) * 192 + 64 + jj]
                     + part[(4 + ub) * 192 + 64 + jj]  + part[(6 + ub) * 192 + 64 + jj];
            float ih = part[(0 + ub) * 192 + 128 + jj] + part[(2 + ub) * 192 + 128 + jj]
                     + part[(4 + ub) * 192 + 128 + jj] + part[(6 + ub) * 192 + 128 + jj];

            float hold = ((const float*)&hbuf[(p * 2 + ub) * UU + j])[0];
            float z = 1.f / (1.f + expf(-(pz + iz + bz)));
            float g = 1.f / (1.f + expf(-(pr + ir + br)));
            float c = tanhf(ph + g * (ih + bh));
            float hn = z * hold + (1.f - z) * c;
            if (tk == 0) hn = hold;

            unsigned long long hd = pack2(hn, hn);
            uint32_t off = (uint32_t)(((p ^ 1) * 2 + ub) * UU + j) * 8u;
#pragma unroll
            for (int r = 0; r < 4; r++)
                st_cluster_u64(hpeer[r] + off, hd);

            hcat[rb * (2 * UU) + dir * UU + j] = __float2half_rn(hn);
        }
        CLUSTER_ARRIVE();
        CLUSTER_WAIT();
    }
}

// ---------------- host launcher ----------------------------------------------
extern "C" void kernel_launch(void* const* d_in, const int* in_sizes, int n_in,
                              void* d_out, int out_size)
{
    const int*   tokens = (const int*)d_in[0];
    const float* emb    = (const float*)d_in[1];
    const float* W_f    = (const float*)d_in[2];
    const float* U_f    = (const float*)d_in[3];
    const float* b_f    = (const float*)d_in[4];
    const float* W_b    = (const float*)d_in[5];
    const float* U_b    = (const float*)d_in[6];
    const float* b_b    = (const float*)d_in[7];
    const float* W1     = (const float*)d_in[8];
    const float* b1     = (const float*)d_in[9];
    const float* W2     = (const float*)d_in[10];
    const float* b2     = (const float*)d_in[11];
    float* out = (float*)d_out;

    __half *w1h, *w2t, *embh, *wcatt, *hcat, *wfth;
    float *bcat, *embw, *bfv, *bpart, *uperm;
    cudaGetSymbolAddress((void**)&w1h,   g_w1h);
    cudaGetSymbolAddress((void**)&w2t,   g_w2t);
    cudaGetSymbolAddress((void**)&embh,  g_embh);
    cudaGetSymbolAddress((void**)&wcatt, g_wcatt);
    cudaGetSymbolAddress((void**)&bcat,  g_bcat);
    cudaGetSymbolAddress((void**)&embw,  g_embw);
    cudaGetSymbolAddress((void**)&hcat,  g_hcat);
    cudaGetSymbolAddress((void**)&wfth,  g_wfth);
    cudaGetSymbolAddress((void**)&bfv,   g_bf);
    cudaGetSymbolAddress((void**)&bpart, g_bpart);
    cudaGetSymbolAddress((void**)&uperm, g_uperm);

    cudaFuncSetAttribute(gemm_h<0>, cudaFuncAttributeMaxDynamicSharedMemorySize, HGE_SMEM);
    cudaFuncSetAttribute(gemm_h<1>, cudaFuncAttributeMaxDynamicSharedMemorySize, HGE_SMEM);
    cudaFuncSetAttribute(gru_scan,  cudaFuncAttributeMaxDynamicSharedMemorySize, GRU_SMEM);

    // 1) prep: fp16 conversions + transposes
    cvt_f16<<<(2 * UU * VV / 4 + 255) / 256, 256>>>((const float4*)W1, (uint2*)w1h, 2 * UU * VV / 4);
    transpose_f16<<<dim3(VV / 32, VV / 32), dim3(32, 8)>>>(W2, w2t);
    cvt_f16<<<(VV * DD / 4 + 255) / 256, 256>>>((const float4*)emb, (uint2*)embh, VV * DD / 4);
    build_wcat<<<(H6 * DD + 255) / 256, 256>>>(W_f, W_b, b_f, b_b, wcatt, bcat);
    permute_u<<<(2 * 4 * UU * 192 + 255) / 256, 256>>>(U_f, U_b, uperm);

    // 2) WfT = fp16((W1@W2)^T) = W2^T @ W1^T-asB  [8000, 512]
    {
        int mtiles = (VV + HBM_ - 1) / HBM_;     // 63
        int ntiles = (2 * UU) / HBN_;            // 2
        gemm_h<1><<<mtiles * ntiles, 256, HGE_SMEM>>>(w2t, w1h, nullptr, wfth,
                                                      VV, 2 * UU, VV);
    }
    // fused bias: bf = b1 @ W2 + b2 (exact fp32, K split 32 ways)
    bias_fuse_part<<<dim3((VV + 127) / 128, 32), 128>>>(b1, W2, bpart);
    bias_fuse_reduce<<<(VV + 127) / 128, 128>>>(bpart, b2, bfv);

    // 3) embW = emb @ [W_f|W_b] + bias   [8000, 1536] fp32
    {
        int mtiles = (VV + HBM_ - 1) / HBM_;     // 63
        int ntiles = H6 / HBN_;                  // 6
        gemm_h<0><<<mtiles * ntiles, 256, HGE_SMEM>>>(embh, wcatt, bcat, embw,
                                                      VV, H6, DD);
    }

    // 4) clustered bidirectional GRU scan (fp16 hcat out)
    gru_scan<<<128, GRU_THREADS, GRU_SMEM>>>(embw, uperm, b_f + H3, b_b + H3,
                                             tokens, hcat);

    // 5) logits = hcat @ Wf + bf -> output  (B = WfT [8000,512] n-major)
    {
        int mtiles = MR / HBM_;                  // 64
        int ntiles = (VV + HBN_ - 1) / HBN_;     // 32
        gemm_h<0><<<mtiles * ntiles, 256, HGE_SMEM>>>(hcat, wfth, bfv, out,
                                                      MR, VV, 2 * UU);
    }
}

// round 10
// speedup vs baseline: 2.6280x; 1.1418x over previous
#include <cuda_runtime.h>
#include <cuda_fp16.h>
#include <cstdint>

#define VV 8000
#define DD 128
#define UU 256
#define BB 32
#define SS 256
#define H3 768
#define H6 1536
#define MR 8192   // B*S

// ---------------- scratch (static device allocations; no cudaMalloc) ---------
__device__ __align__(128) __half g_w1h[2 * UU * VV];    // fp16(W1) [512,8000]
__device__ __align__(128) __half g_w2t[VV * VV];        // fp16(W2^T) [8000,8000]
__device__ __align__(128) __half g_embh[VV * DD];       // fp16(emb)
__device__ __align__(128) __half g_wcatt[H6 * DD];      // fp16([W_f|W_b]^T) [1536,128]
__device__ __align__(128) float  g_bcat[H6];
__device__ __align__(128) float  g_embw[VV * H6];       // emb proj + bias (fp32)
__device__ __align__(128) __half g_hcat[MR * 2 * UU];   // fp16 GRU outputs
__device__ __align__(128) __half g_wfth[VV * 2 * UU];   // fp16((W1@W2)^T) [8000,512]
__device__ __align__(128) float  g_bf[VV];
__device__ __align__(128) float  g_uperm[2 * 4 * UU * 192];

// packed f32x2 helpers (sm_103a)
__device__ __forceinline__ unsigned long long pack2(float x, float y) {
    unsigned long long r;
    asm("mov.b64 %0, {%1,%2};" : "=l"(r) : "f"(x), "f"(y));
    return r;
}
__device__ __forceinline__ float2 unpack2(unsigned long long v) {
    float2 r;
    asm("mov.b64 {%0,%1}, %2;" : "=f"(r.x), "=f"(r.y) : "l"(v));
    return r;
}
#define FMA2(acc, a, b) \
    asm("fma.rn.f32x2 %0, %1, %2, %0;" : "+l"(acc) : "l"(a), "l"(b))

// DSMEM / cluster helpers
__device__ __forceinline__ uint32_t mapa_u32(uint32_t laddr, uint32_t rank) {
    uint32_t r;
    asm("mapa.shared::cluster.u32 %0, %1, %2;" : "=r"(r) : "r"(laddr), "r"(rank));
    return r;
}
__device__ __forceinline__ void st_cluster_u64(uint32_t addr, unsigned long long v) {
    asm volatile("st.shared::cluster.u64 [%0], %1;" :: "r"(addr), "l"(v) : "memory");
}
#define CLUSTER_ARRIVE() asm volatile("barrier.cluster.arrive.aligned;" ::: "memory")
#define CLUSTER_WAIT()   asm volatile("barrier.cluster.wait.aligned;" ::: "memory")

// ---------------- prep kernels -------------------------------------------------
__global__ void cvt_f16(const float4* __restrict__ in, uint2* __restrict__ out, int n4) {
    int i = blockIdx.x * 256 + threadIdx.x;
    if (i < n4) {
        float4 v = in[i];
        __half2 h0 = __floats2half2_rn(v.x, v.y);
        __half2 h1 = __floats2half2_rn(v.z, v.w);
        uint2 r;
        r.x = *reinterpret_cast<uint32_t*>(&h0);
        r.y = *reinterpret_cast<uint32_t*>(&h1);
        out[i] = r;
    }
}

// W2 [8000,8000] fp32 -> fp16(W2^T)
__global__ void transpose_f16(const float* __restrict__ in, __half* __restrict__ out) {
    __shared__ float t[32][33];
    int bx = blockIdx.x * 32;
    int by = blockIdx.y * 32;
    int x = threadIdx.x, y0 = threadIdx.y;
#pragma unroll
    for (int dy = 0; dy < 32; dy += 8)
        t[y0 + dy][x] = in[(size_t)(by + y0 + dy) * VV + bx + x];
    __syncthreads();
#pragma unroll
    for (int dy = 0; dy < 32; dy += 8)
        out[(size_t)(bx + y0 + dy) * VV + by + x] = __float2half_rn(t[x][y0 + dy]);
}

// [W_f|W_b]^T as fp16 [1536 n][128 k] + bias concat
__global__ void build_wcat(const float* __restrict__ Wf_, const float* __restrict__ Wb_,
                           const float* __restrict__ bf_, const float* __restrict__ bb_,
                           __half* __restrict__ wcatt, float* __restrict__ bcat) {
    int i = blockIdx.x * 256 + threadIdx.x;
    if (i < H6 * DD) {
        int n = i / DD, k = i % DD;
        float v = (n < H3) ? Wf_[k * H3 + n] : Wb_[k * H3 + (n - H3)];
        wcatt[i] = __float2half_rn(v);
    }
    if (i < H6)
        bcat[i] = (i < H3) ? bf_[i] : bb_[i - H3];
}

__global__ void permute_u(const float* __restrict__ Uf, const float* __restrict__ Ub,
                          float* __restrict__ uperm) {
    int idx = blockIdx.x * 256 + threadIdx.x;
    if (idx >= 2 * 4 * UU * 192) return;
    int c = idx % 192;
    int k = (idx / 192) % UU;
    int r = (idx / (192 * UU)) % 4;
    int dir = idx / (192 * UU * 4);
    const float* Um = dir ? Ub : Uf;
    int col = (c < 64) ? (64 * r + c)
            : (c < 128) ? (UU + 64 * r + (c - 64))
                        : (2 * UU + 64 * r + (c - 128));
    uperm[idx] = Um[k * H3 + col];
}

// bf[n] = b2[n] + sum_v b1[v]*w2t[n][v]  — one warp per n, fp16 W2^T rows
__global__ void __launch_bounds__(256) bias_fuse_w(
    const float* __restrict__ b1v, const __half* __restrict__ w2t,
    const float* __restrict__ b2v, float* __restrict__ bf)
{
    int n = blockIdx.x * 8 + (threadIdx.x >> 5);
    int lane = threadIdx.x & 31;
    const __half2* row = (const __half2*)(w2t + (size_t)n * VV);
    const float2* b1p = (const float2*)b1v;
    float acc = 0.f;
#pragma unroll 5
    for (int i = 0; i < VV / 64; i++) {          // 125 iters
        int idx = i * 32 + lane;
        float2 f = __half22float2(row[idx]);
        float2 bb = b1p[idx];
        acc += bb.x * f.x + bb.y * f.y;
    }
#pragma unroll
    for (int off = 16; off > 0; off >>= 1)
        acc += __shfl_xor_sync(0xFFFFFFFF, acc, off);
    if (lane == 0) bf[n] = acc + b2v[n];
}

// ---------------- fp16 GEMM (mma.sync m16n8k16, fp32 accum) -------------------
#define HBM_ 128
#define HBN_ 256
#define HBK_ 32
#define HNST 4
#define HROWB 80
#define HASB (HBM_ * HROWB)
#define HBSB (HBN_ * HROWB)
#define HSTG (HASB + HBSB)
#define HGE_SMEM (HNST * HSTG)

template <int OUTF16>
__global__ void __launch_bounds__(256) gemm_h(
    const __half* __restrict__ A, const __half* __restrict__ Bt,
    const float* __restrict__ bias, void* __restrict__ Cv,
    int M, int N, int K)
{
    extern __shared__ __align__(16) unsigned char sm[];

    int ntiles = (N + HBN_ - 1) / HBN_;
    int mt = blockIdx.x / ntiles, nt = blockIdx.x % ntiles;
    int m0 = mt * HBM_, n0 = nt * HBN_;

    int tid = threadIdx.x;
    int lane = tid & 31;
    int wid = tid >> 5;
    int wm = wid >> 2;
    int wn = wid & 3;
    int g = lane >> 2;
    int t4 = lane & 3;

    uint32_t sbase = (uint32_t)__cvta_generic_to_shared(sm);

    float acc[4][8][4];
#pragma unroll
    for (int a = 0; a < 4; a++)
#pragma unroll
        for (int b = 0; b < 8; b++)
#pragma unroll
            for (int c = 0; c < 4; c++) acc[a][b][c] = 0.f;

    const int KT = K / HBK_;

    auto issue = [&](int kt, int slot) {
        int k0 = kt * HBK_;
        uint32_t ab = sbase + slot * HSTG;
        uint32_t bb = ab + HASB;
#pragma unroll
        for (int i = 0; i < 2; i++) {
            int ch = tid + i * 256;
            int r = ch >> 2, c16 = ch & 3;
            int ra = m0 + r; if (ra >= M) ra = M - 1;
            const __half* src = A + (size_t)ra * K + k0 + c16 * 8;
            uint32_t dst = ab + (uint32_t)(r * HROWB + c16 * 16);
            asm volatile("cp.async.cg.shared.global [%0],[%1],16;\n" :: "r"(dst), "l"(src));
        }
#pragma unroll
        for (int i = 0; i < 4; i++) {
            int ch = tid + i * 256;
            int r = ch >> 2, c16 = ch & 3;
            int nb = n0 + r;
            int sz = (nb < N) ? 16 : 0;
            if (nb >= N) nb = N - 1;
            const __half* src = Bt + (size_t)nb * K + k0 + c16 * 8;
            uint32_t dst = bb + (uint32_t)(r * HROWB + c16 * 16);
            asm volatile("cp.async.cg.shared.global [%0],[%1],16,%2;\n" :: "r"(dst), "l"(src), "r"(sz));
        }
        asm volatile("cp.async.commit_group;\n");
    };

    auto docompute = [&](int slot) {
        const unsigned char* As = sm + slot * HSTG;
        const unsigned char* Bs = As + HASB;
#pragma unroll
        for (int kk = 0; kk < 2; kk++) {
            int kb = kk * 32 + t4 * 4;
            uint32_t af[4][4];
#pragma unroll
            for (int mi = 0; mi < 4; mi++) {
                int row = wm * 64 + mi * 16 + g;
                const unsigned char* p = As + row * HROWB + kb;
                af[mi][0] = *(const uint32_t*)(p);
                af[mi][1] = *(const uint32_t*)(p + 8 * HROWB);
                af[mi][2] = *(const uint32_t*)(p + 16);
                af[mi][3] = *(const uint32_t*)(p + 8 * HROWB + 16);
            }
            uint32_t bf[8][2];
#pragma unroll
            for (int ni = 0; ni < 8; ni++) {
                int nr = wn * 64 + ni * 8 + g;
                const unsigned char* p = Bs + nr * HROWB + kb;
                bf[ni][0] = *(const uint32_t*)(p);
                bf[ni][1] = *(const uint32_t*)(p + 16);
            }
#pragma unroll
            for (int mi = 0; mi < 4; mi++)
#pragma unroll
                for (int ni = 0; ni < 8; ni++) {
                    asm volatile(
                        "mma.sync.aligned.m16n8k16.row.col.f32.f16.f16.f32 "
                        "{%0,%1,%2,%3},{%4,%5,%6,%7},{%8,%9},{%0,%1,%2,%3};\n"
                        : "+f"(acc[mi][ni][0]), "+f"(acc[mi][ni][1]),
                          "+f"(acc[mi][ni][2]), "+f"(acc[mi][ni][3])
                        : "r"(af[mi][0]), "r"(af[mi][1]), "r"(af[mi][2]), "r"(af[mi][3]),
                          "r"(bf[ni][0]), "r"(bf[ni][1]));
                }
        }
    };

    issue(0, 0);
    if (KT > 1) issue(1, 1);
    if (KT > 2) issue(2, 2);

#pragma unroll 1
    for (int kt = 0; kt < KT; kt++) {
        if (kt + 1 < KT) {
            asm volatile("cp.async.wait_group %0;\n" :: "n"(HNST - 2));
        } else {
            asm volatile("cp.async.wait_group 0;\n");
        }
        __syncthreads();
        if (kt + HNST - 1 < KT)
            issue(kt + HNST - 1, (kt + HNST - 1) & (HNST - 1));
        docompute(kt & (HNST - 1));
    }

#pragma unroll
    for (int ni = 0; ni < 8; ni++) {
        int c = n0 + wn * 64 + ni * 8 + t4 * 2;
        if (c >= N) continue;
        float b0v = 0.f, b1v = 0.f;
        if (!OUTF16) { b0v = bias[c]; b1v = bias[c + 1]; }
#pragma unroll
        for (int mi = 0; mi < 4; mi++) {
            int r = m0 + wm * 64 + mi * 16 + g;
            if (r >= M) continue;
            if (OUTF16) {
                __half* C = (__half*)Cv;
                __half2 h0 = __floats2half2_rn(acc[mi][ni][0], acc[mi][ni][1]);
                *reinterpret_cast<__half2*>(&C[(size_t)r * N + c]) = h0;
                if (r + 8 < M) {
                    __half2 h1 = __floats2half2_rn(acc[mi][ni][2], acc[mi][ni][3]);
                    *reinterpret_cast<__half2*>(&C[(size_t)(r + 8) * N + c]) = h1;
                }
            } else {
                float* C = (float*)Cv;
                *reinterpret_cast<float2*>(&C[(size_t)r * N + c]) =
                    make_float2(acc[mi][ni][0] + b0v, acc[mi][ni][1] + b1v);
                if (r + 8 < M)
                    *reinterpret_cast<float2*>(&C[(size_t)(r + 8) * N + c]) =
                        make_float2(acc[mi][ni][2] + b0v, acc[mi][ni][3] + b1v);
            }
        }
    }
}

// ---------------- clustered bidirectional masked GRU scan ---------------------
// R10: half of each thread's U slice lives permanently in registers (64 f32x2),
// halving smem crossbar traffic; cluster barrier split arrive/wait so the wait
// overlaps the global prefetch. Accumulation order identical to R9.
#define GRU_THREADS 192
#define GRU_SM_US   (UU * 192 * 4)
#define GRU_SM_PART (4 * 2 * 192 * 4)
#define GRU_SM_H    (2 * 2 * UU * 8)
#define GRU_SMEM    (GRU_SM_US + GRU_SM_PART + GRU_SM_H)

__global__ void __launch_bounds__(GRU_THREADS, 1) __cluster_dims__(4, 1, 1)
gru_scan(const float* __restrict__ embW, const float* __restrict__ uperm,
         const float* __restrict__ bf1, const float* __restrict__ bb1,
         const int* __restrict__ tokens, __half* __restrict__ hcat)
{
    extern __shared__ __align__(16) unsigned char smraw[];
    float* Us   = (float*)smraw;
    float* part = (float*)(smraw + GRU_SM_US);
    unsigned long long* hbuf =
        (unsigned long long*)(smraw + GRU_SM_US + GRU_SM_PART);

    int tid  = threadIdx.x;
    int cid  = blockIdx.x >> 2;
    int rank = blockIdx.x & 3;
    int bp   = cid & 15;
    int dir  = cid >> 4;
    int b0   = bp * 2;

    const float* bv = dir ? bb1 : bf1;

    {
        const float4* src = (const float4*)(uperm + (size_t)(dir * 4 + rank) * UU * 192);
        float4* dst = (float4*)Us;
        for (int i = tid; i < UU * 192 / 4; i += GRU_THREADS) dst[i] = src[i];
        for (int i = tid; i < 2 * 2 * UU; i += GRU_THREADS) hbuf[i] = 0ull;
    }
    __syncthreads();

    int kc = tid / 48;
    int ct = tid % 48;
    int k0 = kc * 64;

    const ulonglong2* U2 = (const ulonglong2*)Us;

    // register-resident U: k in [k0, k0+32), 2 col-pairs per k
    ulonglong2 ur[32];
#pragma unroll
    for (int kk = 0; kk < 32; kk++)
        ur[kk] = U2[(size_t)(k0 + kk) * 48 + ct];

    int jj = tid & 63;
    int ub = tid >> 6;
    int j  = rank * 64 + jj;
    float bz = 0.f, br = 0.f, bh = 0.f;
    if (tid < 128) { bz = bv[j]; br = bv[UU + j]; bh = bv[2 * UU + j]; }

    uint32_t hl = (uint32_t)__cvta_generic_to_shared(hbuf);
    uint32_t hpeer[4];
#pragma unroll
    for (int r = 0; r < 4; r++) hpeer[r] = mapa_u32(hl, r);

    // full cluster sync (smem ready), then pre-arm the phase for step 0's wait
    CLUSTER_ARRIVE();
    CLUSTER_WAIT();
    CLUSTER_ARRIVE();

    for (int i = 0; i < SS; i++) {
        int s = dir ? (SS - 1 - i) : i;
        int p = i & 1;
        size_t rb = (size_t)b0 * SS + s + (size_t)ub * SS;

        // global prefetch issues BEFORE the cluster wait (overlaps barrier)
        float pz = 0.f, pr = 0.f, ph = 0.f; int tk = 1;
        if (tid < 128) {
            tk = tokens[rb];
            const float* xr = embW + (size_t)tk * H6 + dir * H3;
            pz = xr[j]; pr = xr[UU + j]; ph = xr[2 * UU + j];
        }

        CLUSTER_WAIT();   // h(p) from all CTAs now visible

        {
            unsigned long long a00 = 0, a01 = 0, a10 = 0, a11 = 0;
            const ulonglong2* h0 = (const ulonglong2*)(hbuf + (p * 2 + 0) * UU) + kc * 32;
            const ulonglong2* h1 = (const ulonglong2*)(hbuf + (p * 2 + 1) * UU) + kc * 32;
            // register part: k = k0 .. k0+32
#pragma unroll
            for (int kk = 0; kk < 16; kk++) {
                ulonglong2 uA = ur[2 * kk];
                ulonglong2 uB = ur[2 * kk + 1];
                ulonglong2 hA = h0[kk];
                ulonglong2 hB = h1[kk];
                FMA2(a00, uA.x, hA.x); FMA2(a01, uA.y, hA.x);
                FMA2(a10, uA.x, hB.x); FMA2(a11, uA.y, hB.x);
                FMA2(a00, uB.x, hA.y); FMA2(a01, uB.y, hA.y);
                FMA2(a10, uB.x, hB.y); FMA2(a11, uB.y, hB.y);
            }
            // smem part: k = k0+32 .. k0+64
            const ulonglong2* up = U2 + (size_t)(k0 + 32) * 48 + ct;
#pragma unroll 4
            for (int kk = 16; kk < 32; kk++) {
                ulonglong2 uA = up[0];
                ulonglong2 uB = up[48];
                up += 96;
                ulonglong2 hA = h0[kk];
                ulonglong2 hB = h1[kk];
                FMA2(a00, uA.x, hA.x); FMA2(a01, uA.y, hA.x);
                FMA2(a10, uA.x, hB.x); FMA2(a11, uA.y, hB.x);
                FMA2(a00, uB.x, hA.y); FMA2(a01, uB.y, hA.y);
                FMA2(a10, uB.x, hB.y); FMA2(a11, uB.y, hB.y);
            }
            float2 p00 = unpack2(a00), p01 = unpack2(a01);
            float2 p10 = unpack2(a10), p11 = unpack2(a11);
            ((float4*)(part + (kc * 2 + 0) * 192))[ct] = make_float4(p00.x, p00.y, p01.x, p01.y);
            ((float4*)(part + (kc * 2 + 1) * 192))[ct] = make_float4(p10.x, p10.y, p11.x, p11.y);
        }
        __syncthreads();

        float hn = 0.f;
        if (tid < 128) {
            float iz = part[(0 + ub) * 192 + jj]       + part[(2 + ub) * 192 + jj]
                     + part[(4 + ub) * 192 + jj]       + part[(6 + ub) * 192 + jj];
            float ir = part[(0 + ub) * 192 + 64 + jj]  + part[(2 + ub) * 192 + 64 + jj]
                     + part[(4 + ub) * 192 + 64 + jj]  + part[(6 + ub) * 192 + 64 + jj];
            float ih = part[(0 + ub) * 192 + 128 + jj] + part[(2 + ub) * 192 + 128 + jj]
                     + part[(4 + ub) * 192 + 128 + jj] + part[(6 + ub) * 192 + 128 + jj];

            float hold = ((const float*)&hbuf[(p * 2 + ub) * UU + j])[0];
            float z = 1.f / (1.f + __expf(-(pz + iz + bz)));
            float g = 1.f / (1.f + __expf(-(pr + ir + br)));
            float c = tanhf(ph + g * (ih + bh));
            hn = z * hold + (1.f - z) * c;
            if (tk == 0) hn = hold;

            unsigned long long hd = pack2(hn, hn);
            uint32_t off = (uint32_t)(((p ^ 1) * 2 + ub) * UU + j) * 8u;
#pragma unroll
            for (int r = 0; r < 4; r++)
                st_cluster_u64(hpeer[r] + off, hd);
        }
        CLUSTER_ARRIVE();   // release the h stores (all threads)
        if (tid < 128)
            hcat[rb * (2 * UU) + dir * UU + j] = __float2half_rn(hn);
    }
    CLUSTER_WAIT();   // pair the final arrive before exit
}

// ---------------- host launcher ----------------------------------------------
extern "C" void kernel_launch(void* const* d_in, const int* in_sizes, int n_in,
                              void* d_out, int out_size)
{
    const int*   tokens = (const int*)d_in[0];
    const float* emb    = (const float*)d_in[1];
    const float* W_f    = (const float*)d_in[2];
    const float* U_f    = (const float*)d_in[3];
    const float* b_f    = (const float*)d_in[4];
    const float* W_b    = (const float*)d_in[5];
    const float* U_b    = (const float*)d_in[6];
    const float* b_b    = (const float*)d_in[7];
    const float* W1     = (const float*)d_in[8];
    const float* b1     = (const float*)d_in[9];
    const float* W2     = (const float*)d_in[10];
    const float* b2     = (const float*)d_in[11];
    float* out = (float*)d_out;

    __half *w1h, *w2t, *embh, *wcatt, *hcat, *wfth;
    float *bcat, *embw, *bfv, *uperm;
    cudaGetSymbolAddress((void**)&w1h,   g_w1h);
    cudaGetSymbolAddress((void**)&w2t,   g_w2t);
    cudaGetSymbolAddress((void**)&embh,  g_embh);
    cudaGetSymbolAddress((void**)&wcatt, g_wcatt);
    cudaGetSymbolAddress((void**)&bcat,  g_bcat);
    cudaGetSymbolAddress((void**)&embw,  g_embw);
    cudaGetSymbolAddress((void**)&hcat,  g_hcat);
    cudaGetSymbolAddress((void**)&wfth,  g_wfth);
    cudaGetSymbolAddress((void**)&bfv,   g_bf);
    cudaGetSymbolAddress((void**)&uperm, g_uperm);

    cudaFuncSetAttribute(gemm_h<0>, cudaFuncAttributeMaxDynamicSharedMemorySize, HGE_SMEM);
    cudaFuncSetAttribute(gemm_h<1>, cudaFuncAttributeMaxDynamicSharedMemorySize, HGE_SMEM);
    cudaFuncSetAttribute(gru_scan,  cudaFuncAttributeMaxDynamicSharedMemorySize, GRU_SMEM);

    // 1) prep: fp16 conversions + transposes
    cvt_f16<<<(2 * UU * VV / 4 + 255) / 256, 256>>>((const float4*)W1, (uint2*)w1h, 2 * UU * VV / 4);
    transpose_f16<<<dim3(VV / 32, VV / 32), dim3(32, 8)>>>(W2, w2t);
    cvt_f16<<<(VV * DD / 4 + 255) / 256, 256>>>((const float4*)emb, (uint2*)embh, VV * DD / 4);
    build_wcat<<<(H6 * DD + 255) / 256, 256>>>(W_f, W_b, b_f, b_b, wcatt, bcat);
    permute_u<<<(2 * 4 * UU * 192 + 255) / 256, 256>>>(U_f, U_b, uperm);

    // 2) WfT = fp16((W1@W2)^T) = W2^T @ W1-asB  [8000, 512]
    {
        int mtiles = (VV + HBM_ - 1) / HBM_;     // 63
        int ntiles = (2 * UU) / HBN_;            // 2
        gemm_h<1><<<mtiles * ntiles, 256, HGE_SMEM>>>(w2t, w1h, nullptr, wfth,
                                                      VV, 2 * UU, VV);
    }
    // fused bias: bf = b1 @ W2 + b2 (fp16 W2^T, warp per row)
    bias_fuse_w<<<VV / 8, 256>>>(b1, w2t, b2, bfv);

    // 3) embW = emb @ [W_f|W_b] + bias   [8000, 1536] fp32
    {
        int mtiles = (VV + HBM_ - 1) / HBM_;     // 63
        int ntiles = H6 / HBN_;                  // 6
        gemm_h<0><<<mtiles * ntiles, 256, HGE_SMEM>>>(embh, wcatt, bcat, embw,
                                                      VV, H6, DD);
    }

    // 4) clustered bidirectional GRU scan (RF-resident U half)
    gru_scan<<<128, GRU_THREADS, GRU_SMEM>>>(embw, uperm, b_f + H3, b_b + H3,
                                             tokens, hcat);

    // 5) logits = hcat @ Wf + bf -> output  (B = WfT [8000,512] n-major)
    {
        int mtiles = MR / HBM_;                  // 64
        int ntiles = (VV + HBN_ - 1) / HBN_;     // 32
        gemm_h<0><<<mtiles * ntiles, 256, HGE_SMEM>>>(hcat, wfth, bfv, out,
                                                      MR, VV, 2 * UU);
    }
}

// round 11
// speedup vs baseline: 2.6742x; 1.0176x over previous
#include <cuda_runtime.h>
#include <cuda_fp16.h>
#include <cstdint>

#define VV 8000
#define DD 128
#define UU 256
#define BB 32
#define SS 256
#define H3 768
#define H6 1536
#define MR 8192   // B*S

// ---------------- scratch (static device allocations; no cudaMalloc) ---------
__device__ __align__(128) __half g_w1h[2 * UU * VV];    // fp16(W1) [512,8000]
__device__ __align__(128) __half g_w2t[VV * VV];        // fp16(W2^T) [8000,8000]
__device__ __align__(128) __half g_embh[VV * DD];       // fp16(emb)
__device__ __align__(128) __half g_wcatt[H6 * DD];      // fp16([W_f|W_b]^T)
__device__ __align__(128) float  g_bcat[H6];
__device__ __align__(128) float  g_embw[VV * H6];       // emb proj + bias (fp32)
__device__ __align__(128) __half g_hcat[MR * 2 * UU];   // fp16 GRU outputs
__device__ __align__(128) __half g_wfth[VV * 2 * UU];   // fp16((W1@W2)^T) [8000,512]
__device__ __align__(128) float  g_bf[VV];
__device__ __align__(128) float  g_uperm[2 * 4 * UU * 192];

// packed f32x2 helpers (sm_103a)
__device__ __forceinline__ unsigned long long pack2(float x, float y) {
    unsigned long long r;
    asm("mov.b64 %0, {%1,%2};" : "=l"(r) : "f"(x), "f"(y));
    return r;
}
__device__ __forceinline__ float2 unpack2(unsigned long long v) {
    float2 r;
    asm("mov.b64 {%0,%1}, %2;" : "=f"(r.x), "=f"(r.y) : "l"(v));
    return r;
}
#define FMA2(acc, a, b) \
    asm("fma.rn.f32x2 %0, %1, %2, %0;" : "+l"(acc) : "l"(a), "l"(b))

// DSMEM / cluster helpers
__device__ __forceinline__ uint32_t mapa_u32(uint32_t laddr, uint32_t rank) {
    uint32_t r;
    asm("mapa.shared::cluster.u32 %0, %1, %2;" : "=r"(r) : "r"(laddr), "r"(rank));
    return r;
}
__device__ __forceinline__ void st_cluster_u64(uint32_t addr, unsigned long long v) {
    asm volatile("st.shared::cluster.u64 [%0], %1;" :: "r"(addr), "l"(v) : "memory");
}
#define CLUSTER_ARRIVE() asm volatile("barrier.cluster.arrive.aligned;" ::: "memory")
#define CLUSTER_WAIT()   asm volatile("barrier.cluster.wait.aligned;" ::: "memory")

// ---------------- fused prep kernel (4 tasks, index-range dispatch) -----------
#define P_W1   (2 * UU * VV / 4)          // float4 count
#define P_EMB  (VV * DD / 4)
#define P_WCAT (H6 * DD)
#define P_U    (2 * 4 * UU * 192)
#define P_TOT  (P_W1 + P_EMB + P_WCAT + P_U)

__global__ void prep_all(
    const float* __restrict__ W1, __half* __restrict__ w1h,
    const float* __restrict__ emb, __half* __restrict__ embh,
    const float* __restrict__ Wf_, const float* __restrict__ Wb_,
    const float* __restrict__ bfb, const float* __restrict__ bbb,
    __half* __restrict__ wcatt, float* __restrict__ bcat,
    const float* __restrict__ Uf, const float* __restrict__ Ub,
    float* __restrict__ uperm)
{
    int i = blockIdx.x * 256 + threadIdx.x;
    if (i < P_W1) {
        float4 v = ((const float4*)W1)[i];
        __half2 h0 = __floats2half2_rn(v.x, v.y);
        __half2 h1 = __floats2half2_rn(v.z, v.w);
        uint2 r;
        r.x = *reinterpret_cast<uint32_t*>(&h0);
        r.y = *reinterpret_cast<uint32_t*>(&h1);
        ((uint2*)w1h)[i] = r;
        return;
    }
    i -= P_W1;
    if (i < P_EMB) {
        float4 v = ((const float4*)emb)[i];
        __half2 h0 = __floats2half2_rn(v.x, v.y);
        __half2 h1 = __floats2half2_rn(v.z, v.w);
        uint2 r;
        r.x = *reinterpret_cast<uint32_t*>(&h0);
        r.y = *reinterpret_cast<uint32_t*>(&h1);
        ((uint2*)embh)[i] = r;
        return;
    }
    i -= P_EMB;
    if (i < P_WCAT) {
        int n = i / DD, k = i % DD;
        float v = (n < H3) ? Wf_[k * H3 + n] : Wb_[k * H3 + (n - H3)];
        wcatt[i] = __float2half_rn(v);
        if (i < H6)
            bcat[i] = (i < H3) ? bfb[i] : bbb[i - H3];
        return;
    }
    i -= P_WCAT;
    if (i < P_U) {
        int c = i % 192;
        int k = (i / 192) % UU;
        int r = (i / (192 * UU)) % 4;
        int dir = i / (192 * UU * 4);
        const float* Um = dir ? Ub : Uf;
        int col = (c < 64) ? (64 * r + c)
                : (c < 128) ? (UU + 64 * r + (c - 64))
                            : (2 * UU + 64 * r + (c - 128));
        uperm[i] = Um[k * H3 + col];
    }
}

// W2 [8000,8000] fp32 -> fp16(W2^T)
__global__ void transpose_f16(const float* __restrict__ in, __half* __restrict__ out) {
    __shared__ float t[32][33];
    int bx = blockIdx.x * 32;
    int by = blockIdx.y * 32;
    int x = threadIdx.x, y0 = threadIdx.y;
#pragma unroll
    for (int dy = 0; dy < 32; dy += 8)
        t[y0 + dy][x] = in[(size_t)(by + y0 + dy) * VV + bx + x];
    __syncthreads();
#pragma unroll
    for (int dy = 0; dy < 32; dy += 8)
        out[(size_t)(bx + y0 + dy) * VV + by + x] = __float2half_rn(t[x][y0 + dy]);
}

// ---------------- fp16 GEMM body (mma.sync m16n8k16, fp32 accum) --------------
#define HBM_ 128
#define HBN_ 256
#define HBK_ 32
#define HNST 4
#define HROWB 80
#define HASB (HBM_ * HROWB)
#define HBSB (HBN_ * HROWB)
#define HSTG (HASB + HBSB)
#define HGE_SMEM (HNST * HSTG)

template <int OUTF16>
__device__ __forceinline__ void gemm_body(
    const __half* __restrict__ A, const __half* __restrict__ Bt,
    const float* __restrict__ bias, void* __restrict__ Cv,
    int M, int N, int K, int tile, unsigned char* sm)
{
    int ntiles = (N + HBN_ - 1) / HBN_;
    int mt = tile / ntiles, nt = tile % ntiles;
    int m0 = mt * HBM_, n0 = nt * HBN_;

    int tid = threadIdx.x;
    int lane = tid & 31;
    int wid = tid >> 5;
    int wm = wid >> 2;
    int wn = wid & 3;
    int g = lane >> 2;
    int t4 = lane & 3;

    uint32_t sbase = (uint32_t)__cvta_generic_to_shared(sm);

    float acc[4][8][4];
#pragma unroll
    for (int a = 0; a < 4; a++)
#pragma unroll
        for (int b = 0; b < 8; b++)
#pragma unroll
            for (int c = 0; c < 4; c++) acc[a][b][c] = 0.f;

    const int KT = K / HBK_;

    auto issue = [&](int kt, int slot) {
        int k0 = kt * HBK_;
        uint32_t ab = sbase + slot * HSTG;
        uint32_t bb = ab + HASB;
#pragma unroll
        for (int i = 0; i < 2; i++) {
            int ch = tid + i * 256;
            int r = ch >> 2, c16 = ch & 3;
            int ra = m0 + r; if (ra >= M) ra = M - 1;
            const __half* src = A + (size_t)ra * K + k0 + c16 * 8;
            uint32_t dst = ab + (uint32_t)(r * HROWB + c16 * 16);
            asm volatile("cp.async.cg.shared.global [%0],[%1],16;\n" :: "r"(dst), "l"(src));
        }
#pragma unroll
        for (int i = 0; i < 4; i++) {
            int ch = tid + i * 256;
            int r = ch >> 2, c16 = ch & 3;
            int nb = n0 + r;
            int sz = (nb < N) ? 16 : 0;
            if (nb >= N) nb = N - 1;
            const __half* src = Bt + (size_t)nb * K + k0 + c16 * 8;
            uint32_t dst = bb + (uint32_t)(r * HROWB + c16 * 16);
            asm volatile("cp.async.cg.shared.global [%0],[%1],16,%2;\n" :: "r"(dst), "l"(src), "r"(sz));
        }
        asm volatile("cp.async.commit_group;\n");
    };

    auto docompute = [&](int slot) {
        const unsigned char* As = sm + slot * HSTG;
        const unsigned char* Bs = As + HASB;
#pragma unroll
        for (int kk = 0; kk < 2; kk++) {
            int kb = kk * 32 + t4 * 4;
            uint32_t af[4][4];
#pragma unroll
            for (int mi = 0; mi < 4; mi++) {
                int row = wm * 64 + mi * 16 + g;
                const unsigned char* p = As + row * HROWB + kb;
                af[mi][0] = *(const uint32_t*)(p);
                af[mi][1] = *(const uint32_t*)(p + 8 * HROWB);
                af[mi][2] = *(const uint32_t*)(p + 16);
                af[mi][3] = *(const uint32_t*)(p + 8 * HROWB + 16);
            }
            uint32_t bf[8][2];
#pragma unroll
            for (int ni = 0; ni < 8; ni++) {
                int nr = wn * 64 + ni * 8 + g;
                const unsigned char* p = Bs + nr * HROWB + kb;
                bf[ni][0] = *(const uint32_t*)(p);
                bf[ni][1] = *(const uint32_t*)(p + 16);
            }
#pragma unroll
            for (int mi = 0; mi < 4; mi++)
#pragma unroll
                for (int ni = 0; ni < 8; ni++) {
                    asm volatile(
                        "mma.sync.aligned.m16n8k16.row.col.f32.f16.f16.f32 "
                        "{%0,%1,%2,%3},{%4,%5,%6,%7},{%8,%9},{%0,%1,%2,%3};\n"
                        : "+f"(acc[mi][ni][0]), "+f"(acc[mi][ni][1]),
                          "+f"(acc[mi][ni][2]), "+f"(acc[mi][ni][3])
                        : "r"(af[mi][0]), "r"(af[mi][1]), "r"(af[mi][2]), "r"(af[mi][3]),
                          "r"(bf[ni][0]), "r"(bf[ni][1]));
                }
        }
    };

    issue(0, 0);
    if (KT > 1) issue(1, 1);
    if (KT > 2) issue(2, 2);

#pragma unroll 1
    for (int kt = 0; kt < KT; kt++) {
        if (kt + 1 < KT) {
            asm volatile("cp.async.wait_group %0;\n" :: "n"(HNST - 2));
        } else {
            asm volatile("cp.async.wait_group 0;\n");
        }
        __syncthreads();
        if (kt + HNST - 1 < KT)
            issue(kt + HNST - 1, (kt + HNST - 1) & (HNST - 1));
        docompute(kt & (HNST - 1));
    }

#pragma unroll
    for (int ni = 0; ni < 8; ni++) {
        int c = n0 + wn * 64 + ni * 8 + t4 * 2;
        if (c >= N) continue;
        float b0v = 0.f, b1v = 0.f;
        if (!OUTF16) { b0v = bias[c]; b1v = bias[c + 1]; }
#pragma unroll
        for (int mi = 0; mi < 4; mi++) {
            int r = m0 + wm * 64 + mi * 16 + g;
            if (r >= M) continue;
            if (OUTF16) {
                __half* C = (__half*)Cv;
                __half2 h0 = __floats2half2_rn(acc[mi][ni][0], acc[mi][ni][1]);
                *reinterpret_cast<__half2*>(&C[(size_t)r * N + c]) = h0;
                if (r + 8 < M) {
                    __half2 h1 = __floats2half2_rn(acc[mi][ni][2], acc[mi][ni][3]);
                    *reinterpret_cast<__half2*>(&C[(size_t)(r + 8) * N + c]) = h1;
                }
            } else {
                float* C = (float*)Cv;
                *reinterpret_cast<float2*>(&C[(size_t)r * N + c]) =
                    make_float2(acc[mi][ni][0] + b0v, acc[mi][ni][1] + b1v);
                if (r + 8 < M)
                    *reinterpret_cast<float2*>(&C[(size_t)(r + 8) * N + c]) =
                        make_float2(acc[mi][ni][2] + b0v, acc[mi][ni][3] + b1v);
            }
        }
    }
}

// standalone GEMM for the final logits
__global__ void __launch_bounds__(256) gemm_h0(
    const __half* __restrict__ A, const __half* __restrict__ Bt,
    const float* __restrict__ bias, float* __restrict__ C,
    int M, int N, int K)
{
    extern __shared__ __align__(16) unsigned char sm[];
    gemm_body<0>(A, Bt, bias, C, M, N, K, blockIdx.x, sm);
}

// ---------------- mega1: WfT GEMM + embW GEMM + bias fuse in ONE launch -------
#define NW_TILES 126     // 63 x 2  (WfT: M=8000, N=512)
#define NE_TILES 378     // 63 x 6  (embW: M=8000, N=1536)
#define NB_BLKS  (VV / 8)

__global__ void __launch_bounds__(256) mega1(
    const __half* __restrict__ w2t, const __half* __restrict__ w1h,
    __half* __restrict__ wfth,
    const __half* __restrict__ embh, const __half* __restrict__ wcatt,
    const float* __restrict__ bcat, float* __restrict__ embw,
    const float* __restrict__ b1, const float* __restrict__ b2,
    float* __restrict__ bf)
{
    extern __shared__ __align__(16) unsigned char sm[];
    int b = blockIdx.x;
    if (b < NW_TILES) {
        // WfT = fp16((W1@W2)^T): A = W2^T [8000,8000], Bt = W1 [512,8000]
        gemm_body<1>(w2t, w1h, nullptr, wfth, VV, 2 * UU, VV, b, sm);
    } else if (b < NW_TILES + NE_TILES) {
        // embW = emb @ [W_f|W_b] + bias
        gemm_body<0>(embh, wcatt, bcat, embw, VV, H6, DD, b - NW_TILES, sm);
    } else {
        // bias fuse: bf[n] = b2[n] + sum_v b1[v] * w2t[n][v]; warp per n
        int nb = b - NW_TILES - NE_TILES;
        int n = nb * 8 + (threadIdx.x >> 5);
        int lane = threadIdx.x & 31;
        const __half2* row = (const __half2*)(w2t + (size_t)n * VV);
        const float2* b1p = (const float2*)b1;
        float acc = 0.f;
#pragma unroll 5
        for (int i = 0; i < VV / 64; i++) {
            int idx = i * 32 + lane;
            float2 f = __half22float2(row[idx]);
            float2 bb = b1p[idx];
            acc += bb.x * f.x + bb.y * f.y;
        }
#pragma unroll
        for (int off = 16; off > 0; off >>= 1)
            acc += __shfl_xor_sync(0xFFFFFFFF, acc, off);
        if (lane == 0) bf[n] = acc + b2[n];
    }
}

// ---------------- clustered bidirectional masked GRU scan ---------------------
// R11: 40 of 64 U k-rows register-resident (was 32); smem crossbar 768->576 cyc.
#define GRU_THREADS 192
#define GRU_SM_US   (UU * 192 * 4)
#define GRU_SM_PART (4 * 2 * 192 * 4)
#define GRU_SM_H    (2 * 2 * UU * 8)
#define GRU_SMEM    (GRU_SM_US + GRU_SM_PART + GRU_SM_H)
#define UREG 40

__global__ void __launch_bounds__(GRU_THREADS, 1) __cluster_dims__(4, 1, 1)
gru_scan(const float* __restrict__ embW, const float* __restrict__ uperm,
         const float* __restrict__ bf1, const float* __restrict__ bb1,
         const int* __restrict__ tokens, __half* __restrict__ hcat)
{
    extern __shared__ __align__(16) unsigned char smraw[];
    float* Us   = (float*)smraw;
    float* part = (float*)(smraw + GRU_SM_US);
    unsigned long long* hbuf =
        (unsigned long long*)(smraw + GRU_SM_US + GRU_SM_PART);

    int tid  = threadIdx.x;
    int cid  = blockIdx.x >> 2;
    int rank = blockIdx.x & 3;
    int bp   = cid & 15;
    int dir  = cid >> 4;
    int b0   = bp * 2;

    const float* bv = dir ? bb1 : bf1;

    {
        const float4* src = (const float4*)(uperm + (size_t)(dir * 4 + rank) * UU * 192);
        float4* dst = (float4*)Us;
        for (int i = tid; i < UU * 192 / 4; i += GRU_THREADS) dst[i] = src[i];
        for (int i = tid; i < 2 * 2 * UU; i += GRU_THREADS) hbuf[i] = 0ull;
    }
    __syncthreads();

    int kc = tid / 48;
    int ct = tid % 48;
    int k0 = kc * 64;

    const ulonglong2* U2 = (const ulonglong2*)Us;

    // register-resident U: k in [k0, k0+UREG)
    ulonglong2 ur[UREG];
#pragma unroll
    for (int kk = 0; kk < UREG; kk++)
        ur[kk] = U2[(size_t)(k0 + kk) * 48 + ct];

    int jj = tid & 63;
    int ub = tid >> 6;
    int j  = rank * 64 + jj;
    float bz = 0.f, br = 0.f, bh = 0.f;
    if (tid < 128) { bz = bv[j]; br = bv[UU + j]; bh = bv[2 * UU + j]; }

    uint32_t hl = (uint32_t)__cvta_generic_to_shared(hbuf);
    uint32_t hpeer[4];
#pragma unroll
    for (int r = 0; r < 4; r++) hpeer[r] = mapa_u32(hl, r);

    CLUSTER_ARRIVE();
    CLUSTER_WAIT();
    CLUSTER_ARRIVE();

    for (int i = 0; i < SS; i++) {
        int s = dir ? (SS - 1 - i) : i;
        int p = i & 1;
        size_t rb = (size_t)b0 * SS + s + (size_t)ub * SS;

        float pz = 0.f, pr = 0.f, ph = 0.f; int tk = 1;
        if (tid < 128) {
            tk = tokens[rb];
            const float* xr = embW + (size_t)tk * H6 + dir * H3;
            pz = xr[j]; pr = xr[UU + j]; ph = xr[2 * UU + j];
        }

        CLUSTER_WAIT();

        {
            unsigned long long a00 = 0, a01 = 0, a10 = 0, a11 = 0;
            const ulonglong2* h0 = (const ulonglong2*)(hbuf + (p * 2 + 0) * UU) + kc * 32;
            const ulonglong2* h1 = (const ulonglong2*)(hbuf + (p * 2 + 1) * UU) + kc * 32;
            // register part: k = k0 .. k0+UREG
#pragma unroll
            for (int kk = 0; kk < UREG / 2; kk++) {
                ulonglong2 uA = ur[2 * kk];
                ulonglong2 uB = ur[2 * kk + 1];
                ulonglong2 hA = h0[kk];
                ulonglong2 hB = h1[kk];
                FMA2(a00, uA.x, hA.x); FMA2(a01, uA.y, hA.x);
                FMA2(a10, uA.x, hB.x); FMA2(a11, uA.y, hB.x);
                FMA2(a00, uB.x, hA.y); FMA2(a01, uB.y, hA.y);
                FMA2(a10, uB.x, hB.y); FMA2(a11, uB.y, hB.y);
            }
            // smem part: k = k0+UREG .. k0+64
            const ulonglong2* up = U2 + (size_t)(k0 + UREG) * 48 + ct;
#pragma unroll 4
            for (int kk = UREG / 2; kk < 32; kk++) {
                ulonglong2 uA = up[0];
                ulonglong2 uB = up[48];
                up += 96;
                ulonglong2 hA = h0[kk];
                ulonglong2 hB = h1[kk];
                FMA2(a00, uA.x, hA.x); FMA2(a01, uA.y, hA.x);
                FMA2(a10, uA.x, hB.x); FMA2(a11, uA.y, hB.x);
                FMA2(a00, uB.x, hA.y); FMA2(a01, uB.y, hA.y);
                FMA2(a10, uB.x, hB.y); FMA2(a11, uB.y, hB.y);
            }
            float2 p00 = unpack2(a00), p01 = unpack2(a01);
            float2 p10 = unpack2(a10), p11 = unpack2(a11);
            ((float4*)(part + (kc * 2 + 0) * 192))[ct] = make_float4(p00.x, p00.y, p01.x, p01.y);
            ((float4*)(part + (kc * 2 + 1) * 192))[ct] = make_float4(p10.x, p10.y, p11.x, p11.y);
        }
        __syncthreads();

        float hn = 0.f;
        if (tid < 128) {
            float iz = part[(0 + ub) * 192 + jj]       + part[(2 + ub) * 192 + jj]
                     + part[(4 + ub) * 192 + jj]       + part[(6 + ub) * 192 + jj];
            float ir = part[(0 + ub) * 192 + 64 + jj]  + part[(2 + ub) * 192 + 64 + jj]
                     + part[(4 + ub) * 192 + 64 + jj]  + part[(6 + ub) * 192 + 64 + jj];
            float ih = part[(0 + ub) * 192 + 128 + jj] + part[(2 + ub) * 192 + 128 + jj]
                     + part[(4 + ub) * 192 + 128 + jj] + part[(6 + ub) * 192 + 128 + jj];

            float hold = ((const float*)&hbuf[(p * 2 + ub) * UU + j])[0];
            float z = 1.f / (1.f + __expf(-(pz + iz + bz)));
            float g = 1.f / (1.f + __expf(-(pr + ir + br)));
            float c = tanhf(ph + g * (ih + bh));
            hn = z * hold + (1.f - z) * c;
            if (tk == 0) hn = hold;

            unsigned long long hd = pack2(hn, hn);
            uint32_t off = (uint32_t)(((p ^ 1) * 2 + ub) * UU + j) * 8u;
#pragma unroll
            for (int r = 0; r < 4; r++)
                st_cluster_u64(hpeer[r] + off, hd);
        }
        CLUSTER_ARRIVE();
        if (tid < 128)
            hcat[rb * (2 * UU) + dir * UU + j] = __float2half_rn(hn);
    }
    CLUSTER_WAIT();
}

// ---------------- host launcher ----------------------------------------------
extern "C" void kernel_launch(void* const* d_in, const int* in_sizes, int n_in,
                              void* d_out, int out_size)
{
    const int*   tokens = (const int*)d_in[0];
    const float* emb    = (const float*)d_in[1];
    const float* W_f    = (const float*)d_in[2];
    const float* U_f    = (const float*)d_in[3];
    const float* b_f    = (const float*)d_in[4];
    const float* W_b    = (const float*)d_in[5];
    const float* U_b    = (const float*)d_in[6];
    const float* b_b    = (const float*)d_in[7];
    const float* W1     = (const float*)d_in[8];
    const float* b1     = (const float*)d_in[9];
    const float* W2     = (const float*)d_in[10];
    const float* b2     = (const float*)d_in[11];
    float* out = (float*)d_out;

    __half *w1h, *w2t, *embh, *wcatt, *hcat, *wfth;
    float *bcat, *embw, *bfv, *uperm;
    cudaGetSymbolAddress((void**)&w1h,   g_w1h);
    cudaGetSymbolAddress((void**)&w2t,   g_w2t);
    cudaGetSymbolAddress((void**)&embh,  g_embh);
    cudaGetSymbolAddress((void**)&wcatt, g_wcatt);
    cudaGetSymbolAddress((void**)&bcat,  g_bcat);
    cudaGetSymbolAddress((void**)&embw,  g_embw);
    cudaGetSymbolAddress((void**)&hcat,  g_hcat);
    cudaGetSymbolAddress((void**)&wfth,  g_wfth);
    cudaGetSymbolAddress((void**)&bfv,   g_bf);
    cudaGetSymbolAddress((void**)&uperm, g_uperm);

    cudaFuncSetAttribute(mega1,   cudaFuncAttributeMaxDynamicSharedMemorySize, HGE_SMEM);
    cudaFuncSetAttribute(gemm_h0, cudaFuncAttributeMaxDynamicSharedMemorySize, HGE_SMEM);
    cudaFuncSetAttribute(gru_scan, cudaFuncAttributeMaxDynamicSharedMemorySize, GRU_SMEM);

    // 1) fused prep (W1->fp16, emb->fp16, wcat^T fp16 + bias concat, U permute)
    prep_all<<<(P_TOT + 255) / 256, 256>>>(W1, w1h, emb, embh,
                                           W_f, W_b, b_f, b_b, wcatt, bcat,
                                           U_f, U_b, uperm);
    // 2) W2 -> fp16(W2^T)
    transpose_f16<<<dim3(VV / 32, VV / 32), dim3(32, 8)>>>(W2, w2t);

    // 3) mega: WfT GEMM (126 long tiles first) + embW GEMM (378) + bias (1000)
    mega1<<<NW_TILES + NE_TILES + NB_BLKS, 256, HGE_SMEM>>>(
        w2t, w1h, wfth, embh, wcatt, bcat, embw, b1, b2, bfv);

    // 4) clustered bidirectional GRU scan
    gru_scan<<<128, GRU_THREADS, GRU_SMEM>>>(embw, uperm, b_f + H3, b_b + H3,
                                             tokens, hcat);

    // 5) logits = hcat @ Wf + bf -> output  (B = WfT [8000,512] n-major)
    {
        int mtiles = MR / HBM_;                  // 64
        int ntiles = (VV + HBN_ - 1) / HBN_;     // 32
        gemm_h0<<<mtiles * ntiles, 256, HGE_SMEM>>>(hcat, wfth, bfv, out,
                                                    MR, VV, 2 * UU);
    }
}

// round 12
// speedup vs baseline: 2.6797x; 1.0020x over previous
#include <cuda_runtime.h>
#include <cuda_fp16.h>
#include <cstdint>

#define VV 8000
#define DD 128
#define UU 256
#define BB 32
#define SS 256
#define H3 768
#define H6 1536
#define MR 8192   // B*S
#define KC 1600   // WfT split-K chunk (x5)
#define NSPLIT 5

// ---------------- scratch (static device allocations; no cudaMalloc) ---------
__device__ __align__(128) __half g_w1h[2 * UU * VV];    // fp16(W1) [512,8000]
__device__ __align__(128) __half g_w2t[VV * VV];        // fp16(W2^T) [8000,8000]
__device__ __align__(128) __half g_embh[VV * DD];       // fp16(emb)
__device__ __align__(128) __half g_wcatt[H6 * DD];      // fp16([W_f|W_b]^T)
__device__ __align__(128) float  g_bcat[H6];
__device__ __align__(128) float  g_embw[VV * H6];       // emb proj + bias (fp32)
__device__ __align__(128) __half g_hcat[MR * 2 * UU];   // fp16 GRU outputs
__device__ __align__(128) __half g_wfth[VV * 2 * UU];   // fp16((W1@W2)^T) [8000,512]
__device__ __align__(128) float  g_partk[NSPLIT * VV * 2 * UU];  // split-K partials
__device__ __align__(128) float  g_bf[VV];
__device__ __align__(128) float  g_zb[2 * UU];          // zero bias (never written)
__device__ __align__(128) float  g_uperm[2 * 4 * UU * 192];

// packed f32x2 helpers (sm_103a)
__device__ __forceinline__ unsigned long long pack2(float x, float y) {
    unsigned long long r;
    asm("mov.b64 %0, {%1,%2};" : "=l"(r) : "f"(x), "f"(y));
    return r;
}
__device__ __forceinline__ float2 unpack2(unsigned long long v) {
    float2 r;
    asm("mov.b64 {%0,%1}, %2;" : "=f"(r.x), "=f"(r.y) : "l"(v));
    return r;
}
#define FMA2(acc, a, b) \
    asm("fma.rn.f32x2 %0, %1, %2, %0;" : "+l"(acc) : "l"(a), "l"(b))

// DSMEM / cluster helpers
__device__ __forceinline__ uint32_t mapa_u32(uint32_t laddr, uint32_t rank) {
    uint32_t r;
    asm("mapa.shared::cluster.u32 %0, %1, %2;" : "=r"(r) : "r"(laddr), "r"(rank));
    return r;
}
#define CLUSTER_ARRIVE() asm volatile("barrier.cluster.arrive.aligned;" ::: "memory")
#define CLUSTER_WAIT()   asm volatile("barrier.cluster.wait.aligned;" ::: "memory")

// async remote store with mbarrier tx completion (sm_90+)
#define ST_ASYNC_U64(raddr, v, rmbar) \
    asm volatile("st.async.shared::cluster.mbarrier::complete_tx::bytes.u64 [%0], %1, [%2];" \
                 :: "r"(raddr), "l"(v), "r"(rmbar) : "memory")

#define MBARRIER_INIT(addr, cnt) \
    asm volatile("mbarrier.init.shared.b64 [%0], %1;" :: "r"((uint32_t)(addr)), "r"((uint32_t)(cnt)) : "memory")
#define MBARRIER_EXPECT_TX(addr, tx) \
    asm volatile("mbarrier.arrive.expect_tx.shared.b64 _, [%0], %1;" \
                 :: "r"((uint32_t)(addr)), "r"((uint32_t)(tx)) : "memory")
#define MBARRIER_WAIT_PARITY(addr, par) do {                                   \
    uint32_t _m = (uint32_t)(addr); uint32_t _p = (uint32_t)(par);             \
    asm volatile(                                                              \
        "{\n\t.reg .pred P1;\n\t"                                              \
        "WL_%=:\n\t"                                                           \
        "mbarrier.try_wait.parity.acquire.cta.shared::cta.b64 P1, [%0], %1, 0x989680;\n\t" \
        "@P1 bra.uni WD_%=;\n\t"                                               \
        "bra.uni WL_%=;\n\t"                                                   \
        "WD_%=:\n\t}"                                                          \
        :: "r"(_m), "r"(_p) : "memory");                                       \
} while (0)

// ---------------- fused prep kernel (4 tasks, index-range dispatch) -----------
#define P_W1   (2 * UU * VV / 4)
#define P_EMB  (VV * DD / 4)
#define P_WCAT (H6 * DD)
#define P_U    (2 * 4 * UU * 192)
#define P_TOT  (P_W1 + P_EMB + P_WCAT + P_U)

__global__ void prep_all(
    const float* __restrict__ W1, __half* __restrict__ w1h,
    const float* __restrict__ emb, __half* __restrict__ embh,
    const float* __restrict__ Wf_, const float* __restrict__ Wb_,
    const float* __restrict__ bfb, const float* __restrict__ bbb,
    __half* __restrict__ wcatt, float* __restrict__ bcat,
    const float* __restrict__ Uf, const float* __restrict__ Ub,
    float* __restrict__ uperm)
{
    int i = blockIdx.x * 256 + threadIdx.x;
    if (i < P_W1) {
        float4 v = ((const float4*)W1)[i];
        __half2 h0 = __floats2half2_rn(v.x, v.y);
        __half2 h1 = __floats2half2_rn(v.z, v.w);
        uint2 r;
        r.x = *reinterpret_cast<uint32_t*>(&h0);
        r.y = *reinterpret_cast<uint32_t*>(&h1);
        ((uint2*)w1h)[i] = r;
        return;
    }
    i -= P_W1;
    if (i < P_EMB) {
        float4 v = ((const float4*)emb)[i];
        __half2 h0 = __floats2half2_rn(v.x, v.y);
        __half2 h1 = __floats2half2_rn(v.z, v.w);
        uint2 r;
        r.x = *reinterpret_cast<uint32_t*>(&h0);
        r.y = *reinterpret_cast<uint32_t*>(&h1);
        ((uint2*)embh)[i] = r;
        return;
    }
    i -= P_EMB;
    if (i < P_WCAT) {
        int n = i / DD, k = i % DD;
        float v = (n < H3) ? Wf_[k * H3 + n] : Wb_[k * H3 + (n - H3)];
        wcatt[i] = __float2half_rn(v);
        if (i < H6)
            bcat[i] = (i < H3) ? bfb[i] : bbb[i - H3];
        return;
    }
    i -= P_WCAT;
    if (i < P_U) {
        int c = i % 192;
        int k = (i / 192) % UU;
        int r = (i / (192 * UU)) % 4;
        int dir = i / (192 * UU * 4);
        const float* Um = dir ? Ub : Uf;
        int col = (c < 64) ? (64 * r + c)
                : (c < 128) ? (UU + 64 * r + (c - 64))
                            : (2 * UU + 64 * r + (c - 128));
        uperm[i] = Um[k * H3 + col];
    }
}

// W2 [8000,8000] fp32 -> fp16(W2^T)
__global__ void transpose_f16(const float* __restrict__ in, __half* __restrict__ out) {
    __shared__ float t[32][33];
    int bx = blockIdx.x * 32;
    int by = blockIdx.y * 32;
    int x = threadIdx.x, y0 = threadIdx.y;
#pragma unroll
    for (int dy = 0; dy < 32; dy += 8)
        t[y0 + dy][x] = in[(size_t)(by + y0 + dy) * VV + bx + x];
    __syncthreads();
#pragma unroll
    for (int dy = 0; dy < 32; dy += 8)
        out[(size_t)(bx + y0 + dy) * VV + by + x] = __float2half_rn(t[x][y0 + dy]);
}

// split-K reduce: wfth = fp16(sum of NSPLIT partials)
__global__ void wf_reduce(const float* __restrict__ partk, __half* __restrict__ wfth) {
    int i = blockIdx.x * 256 + threadIdx.x;
    const int n4 = VV * 2 * UU / 4;
    if (i >= n4) return;
    float4 s = ((const float4*)partk)[i];
#pragma unroll
    for (int z = 1; z < NSPLIT; z++) {
        float4 v = ((const float4*)(partk + (size_t)z * VV * 2 * UU))[i];
        s.x += v.x; s.y += v.y; s.z += v.z; s.w += v.w;
    }
    __half2 h0 = __floats2half2_rn(s.x, s.y);
    __half2 h1 = __floats2half2_rn(s.z, s.w);
    uint2 r;
    r.x = *reinterpret_cast<uint32_t*>(&h0);
    r.y = *reinterpret_cast<uint32_t*>(&h1);
    ((uint2*)wfth)[i] = r;
}

// ---------------- fp16 GEMM body (mma.sync m16n8k16, fp32 accum) --------------
#define HBM_ 128
#define HBN_ 256
#define HBK_ 32
#define HNST 4
#define HROWB 80
#define HASB (HBM_ * HROWB)
#define HBSB (HBN_ * HROWB)
#define HSTG (HASB + HBSB)
#define HGE_SMEM (HNST * HSTG)

__device__ __forceinline__ void gemm_body(
    const __half* __restrict__ A, int lda,
    const __half* __restrict__ Bt, int ldb,
    const float* __restrict__ bias, float* __restrict__ C,
    int M, int N, int K, int tile, unsigned char* sm)
{
    int ntiles = (N + HBN_ - 1) / HBN_;
    int mt = tile / ntiles, nt = tile % ntiles;
    int m0 = mt * HBM_, n0 = nt * HBN_;

    int tid = threadIdx.x;
    int lane = tid & 31;
    int wid = tid >> 5;
    int wm = wid >> 2;
    int wn = wid & 3;
    int g = lane >> 2;
    int t4 = lane & 3;

    uint32_t sbase = (uint32_t)__cvta_generic_to_shared(sm);

    float acc[4][8][4];
#pragma unroll
    for (int a = 0; a < 4; a++)
#pragma unroll
        for (int b = 0; b < 8; b++)
#pragma unroll
            for (int c = 0; c < 4; c++) acc[a][b][c] = 0.f;

    const int KT = K / HBK_;

    auto issue = [&](int kt, int slot) {
        int k0 = kt * HBK_;
        uint32_t ab = sbase + slot * HSTG;
        uint32_t bb = ab + HASB;
#pragma unroll
        for (int i = 0; i < 2; i++) {
            int ch = tid + i * 256;
            int r = ch >> 2, c16 = ch & 3;
            int ra = m0 + r; if (ra >= M) ra = M - 1;
            const __half* src = A + (size_t)ra * lda + k0 + c16 * 8;
            uint32_t dst = ab + (uint32_t)(r * HROWB + c16 * 16);
            asm volatile("cp.async.cg.shared.global [%0],[%1],16;\n" :: "r"(dst), "l"(src));
        }
#pragma unroll
        for (int i = 0; i < 4; i++) {
            int ch = tid + i * 256;
            int r = ch >> 2, c16 = ch & 3;
            int nb = n0 + r;
            int sz = (nb < N) ? 16 : 0;
            if (nb >= N) nb = N - 1;
            const __half* src = Bt + (size_t)nb * ldb + k0 + c16 * 8;
            uint32_t dst = bb + (uint32_t)(r * HROWB + c16 * 16);
            asm volatile("cp.async.cg.shared.global [%0],[%1],16,%2;\n" :: "r"(dst), "l"(src), "r"(sz));
        }
        asm volatile("cp.async.commit_group;\n");
    };

    auto docompute = [&](int slot) {
        const unsigned char* As = sm + slot * HSTG;
        const unsigned char* Bs = As + HASB;
#pragma unroll
        for (int kk = 0; kk < 2; kk++) {
            int kb = kk * 32 + t4 * 4;
            uint32_t af[4][4];
#pragma unroll
            for (int mi = 0; mi < 4; mi++) {
                int row = wm * 64 + mi * 16 + g;
                const unsigned char* p = As + row * HROWB + kb;
                af[mi][0] = *(const uint32_t*)(p);
                af[mi][1] = *(const uint32_t*)(p + 8 * HROWB);
                af[mi][2] = *(const uint32_t*)(p + 16);
                af[mi][3] = *(const uint32_t*)(p + 8 * HROWB + 16);
            }
            uint32_t bf[8][2];
#pragma unroll
            for (int ni = 0; ni < 8; ni++) {
                int nr = wn * 64 + ni * 8 + g;
                const unsigned char* p = Bs + nr * HROWB + kb;
                bf[ni][0] = *(const uint32_t*)(p);
                bf[ni][1] = *(const uint32_t*)(p + 16);
            }
#pragma unroll
            for (int mi = 0; mi < 4; mi++)
#pragma unroll
                for (int ni = 0; ni < 8; ni++) {
                    asm volatile(
                        "mma.sync.aligned.m16n8k16.row.col.f32.f16.f16.f32 "
                        "{%0,%1,%2,%3},{%4,%5,%6,%7},{%8,%9},{%0,%1,%2,%3};\n"
                        : "+f"(acc[mi][ni][0]), "+f"(acc[mi][ni][1]),
                          "+f"(acc[mi][ni][2]), "+f"(acc[mi][ni][3])
                        : "r"(af[mi][0]), "r"(af[mi][1]), "r"(af[mi][2]), "r"(af[mi][3]),
                          "r"(bf[ni][0]), "r"(bf[ni][1]));
                }
        }
    };

    issue(0, 0);
    if (KT > 1) issue(1, 1);
    if (KT > 2) issue(2, 2);

#pragma unroll 1
    for (int kt = 0; kt < KT; kt++) {
        if (kt + 1 < KT) {
            asm volatile("cp.async.wait_group %0;\n" :: "n"(HNST - 2));
        } else {
            asm volatile("cp.async.wait_group 0;\n");
        }
        __syncthreads();
        if (kt + HNST - 1 < KT)
            issue(kt + HNST - 1, (kt + HNST - 1) & (HNST - 1));
        docompute(kt & (HNST - 1));
    }

#pragma unroll
    for (int ni = 0; ni < 8; ni++) {
        int c = n0 + wn * 64 + ni * 8 + t4 * 2;
        if (c >= N) continue;
        float b0v = bias[c], b1v = bias[c + 1];
#pragma unroll
        for (int mi = 0; mi < 4; mi++) {
            int r = m0 + wm * 64 + mi * 16 + g;
            if (r >= M) continue;
            *reinterpret_cast<float2*>(&C[(size_t)r * N + c]) =
                make_float2(acc[mi][ni][0] + b0v, acc[mi][ni][1] + b1v);
            if (r + 8 < M)
                *reinterpret_cast<float2*>(&C[(size_t)(r + 8) * N + c]) =
                    make_float2(acc[mi][ni][2] + b0v, acc[mi][ni][3] + b1v);
        }
    }
}

// standalone GEMM (embW projection + final logits)
__global__ void __launch_bounds__(256) gemm_h0(
    const __half* __restrict__ A, int lda, const __half* __restrict__ Bt, int ldb,
    const float* __restrict__ bias, float* __restrict__ C,
    int M, int N, int K)
{
    extern __shared__ __align__(16) unsigned char sm[];
    gemm_body(A, lda, Bt, ldb, bias, C, M, N, K, blockIdx.x, sm);
}

// ---------------- GRU body: mbarrier/st.async synced, cluster of 4 ------------
#define GRU_SM_US   (UU * 192 * 4)              // 196608
#define GRU_SM_PART (4 * 2 * 192 * 4)           // 6144
#define GRU_SM_H    (2 * 2 * UU * 8)            // 8192
#define GRU_SMEM    (GRU_SM_US + GRU_SM_PART + GRU_SM_H + 16)
#define UREG 32

__device__ void gru_body(unsigned char* smraw,
    const float* __restrict__ embW, const float* __restrict__ uperm,
    const float* __restrict__ bf1, const float* __restrict__ bb1,
    const int* __restrict__ tokens, __half* __restrict__ hcat)
{
    float* Us   = (float*)smraw;
    float* part = (float*)(smraw + GRU_SM_US);
    unsigned long long* hbuf =
        (unsigned long long*)(smraw + GRU_SM_US + GRU_SM_PART);
    uint32_t mb0 = (uint32_t)__cvta_generic_to_shared(smraw + GRU_SM_US + GRU_SM_PART + GRU_SM_H);

    int tid  = threadIdx.x;
    int cid  = blockIdx.x >> 2;
    int rank = blockIdx.x & 3;
    int bp   = cid & 15;
    int dir  = cid >> 4;
    int b0   = bp * 2;
    const float* bv = dir ? bb1 : bf1;

    {
        const float4* src = (const float4*)(uperm + (size_t)(dir * 4 + rank) * UU * 192);
        float4* dst = (float4*)Us;
        for (int i = tid; i < UU * 192 / 4; i += 256) dst[i] = src[i];
        for (int i = tid; i < 2 * 2 * UU; i += 256) hbuf[i] = 0ull;
    }
    if (tid == 0) { MBARRIER_INIT(mb0, 1); MBARRIER_INIT(mb0 + 8, 1); }
    __syncthreads();
    CLUSTER_ARRIVE();
    CLUSTER_WAIT();

    bool mv = (tid < 192);
    int kc = mv ? (tid / 48) : 0;
    int ct = mv ? (tid % 48) : 0;
    int k0 = kc * 64;

    const ulonglong2* U2 = (const ulonglong2*)Us;
    ulonglong2 ur[UREG];
    if (mv) {
#pragma unroll
        for (int kk = 0; kk < UREG; kk++)
            ur[kk] = U2[(size_t)(k0 + kk) * 48 + ct];
    }

    int jj = tid & 63;
    int ub = (tid >> 6) & 1;
    int j  = rank * 64 + jj;
    float bz = 0.f, br = 0.f, bh = 0.f;
    if (tid < 128) { bz = bv[j]; br = bv[UU + j]; bh = bv[2 * UU + j]; }

    uint32_t hl = (uint32_t)__cvta_generic_to_shared(hbuf);
    uint32_t hpeer[4], mpeer[4];
#pragma unroll
    for (int r = 0; r < 4; r++) {
        hpeer[r] = mapa_u32(hl, r);
        mpeer[r] = mapa_u32(mb0, r);
    }

    int ph0 = 0, ph1 = 0;

    for (int i = 0; i < SS; i++) {
        int p = i & 1;
        // post expected tx for THIS step's production buffer (before any of our stores)
        if (tid == 0 && i < SS - 1)
            MBARRIER_EXPECT_TX(mb0 + (p ^ 1) * 8, 4096);

        // global prefetch (overlaps the mbarrier wait)
        float pz = 0.f, pr = 0.f, phx = 0.f; int tk = 1;
        size_t rb = 0;
        if (tid < 128) {
            int s = dir ? (SS - 1 - i) : i;
            rb = (size_t)(b0 + ub) * SS + s;
            tk = tokens[rb];
            const float* xr = embW + (size_t)tk * H6 + dir * H3;
            pz = xr[j]; pr = xr[UU + j]; phx = xr[2 * UU + j];
        }

        if (i > 0) {
            if (p == 0) { MBARRIER_WAIT_PARITY(mb0,     ph0); ph0 ^= 1; }
            else        { MBARRIER_WAIT_PARITY(mb0 + 8, ph1); ph1 ^= 1; }
        }

        if (mv) {
            unsigned long long a00 = 0, a01 = 0, a10 = 0, a11 = 0;
            const ulonglong2* h0 = (const ulonglong2*)(hbuf + (p * 2 + 0) * UU) + kc * 32;
            const ulonglong2* h1 = (const ulonglong2*)(hbuf + (p * 2 + 1) * UU) + kc * 32;
#pragma unroll
            for (int kk = 0; kk < UREG / 2; kk++) {
                ulonglong2 uA = ur[2 * kk];
                ulonglong2 uB = ur[2 * kk + 1];
                ulonglong2 hA = h0[kk];
                ulonglong2 hB = h1[kk];
                FMA2(a00, uA.x, hA.x); FMA2(a01, uA.y, hA.x);
                FMA2(a10, uA.x, hB.x); FMA2(a11, uA.y, hB.x);
                FMA2(a00, uB.x, hA.y); FMA2(a01, uB.y, hA.y);
                FMA2(a10, uB.x, hB.y); FMA2(a11, uB.y, hB.y);
            }
            const ulonglong2* up = U2 + (size_t)(k0 + UREG) * 48 + ct;
#pragma unroll 4
            for (int kk = UREG / 2; kk < 32; kk++) {
                ulonglong2 uA = up[0];
                ulonglong2 uB = up[48];
                up += 96;
                ulonglong2 hA = h0[kk];
                ulonglong2 hB = h1[kk];
                FMA2(a00, uA.x, hA.x); FMA2(a01, uA.y, hA.x);
                FMA2(a10, uA.x, hB.x); FMA2(a11, uA.y, hB.x);
                FMA2(a00, uB.x, hA.y); FMA2(a01, uB.y, hA.y);
                FMA2(a10, uB.x, hB.y); FMA2(a11, uB.y, hB.y);
            }
            float2 p00 = unpack2(a00), p01 = unpack2(a01);
            float2 p10 = unpack2(a10), p11 = unpack2(a11);
            ((float4*)(part + (kc * 2 + 0) * 192))[ct] = make_float4(p00.x, p00.y, p01.x, p01.y);
            ((float4*)(part + (kc * 2 + 1) * 192))[ct] = make_float4(p10.x, p10.y, p11.x, p11.y);
        }
        __syncthreads();

        if (tid < 128) {
            float iz = part[(0 + ub) * 192 + jj]       + part[(2 + ub) * 192 + jj]
                     + part[(4 + ub) * 192 + jj]       + part[(6 + ub) * 192 + jj];
            float ir = part[(0 + ub) * 192 + 64 + jj]  + part[(2 + ub) * 192 + 64 + jj]
                     + part[(4 + ub) * 192 + 64 + jj]  + part[(6 + ub) * 192 + 64 + jj];
            float ih = part[(0 + ub) * 192 + 128 + jj] + part[(2 + ub) * 192 + 128 + jj]
                     + part[(4 + ub) * 192 + 128 + jj] + part[(6 + ub) * 192 + 128 + jj];

            float hold = ((const float*)&hbuf[(p * 2 + ub) * UU + j])[0];
            float z = 1.f / (1.f + __expf(-(pz + iz + bz)));
            float g = 1.f / (1.f + __expf(-(pr + ir + br)));
            float c = tanhf(phx + g * (ih + bh));
            float hn = z * hold + (1.f - z) * c;
            if (tk == 0) hn = hold;

            if (i < SS - 1) {
                unsigned long long hd = pack2(hn, hn);
                uint32_t off = (uint32_t)(((p ^ 1) * 2 + ub) * UU + j) * 8u;
                uint32_t mboff = (uint32_t)((p ^ 1) * 8);
#pragma unroll
                for (int r = 0; r < 4; r++)
                    ST_ASYNC_U64(hpeer[r] + off, hd, mpeer[r] + mboff);
            }
            hcat[rb * (2 * UU) + dir * UU + j] = __float2half_rn(hn);
        }
        // no end-of-step barrier: part[] reuse is ordered through the mbarrier
        // (phase completion requires our own st.async, which data-depends on
        //  our part[] reads)
    }
    CLUSTER_ARRIVE();
    CLUSTER_WAIT();
}

// ---------------- mega2: GRU + WfT split-K GEMM + bias fuse, one launch -------
#define NG    128
#define NWFT  (NSPLIT * 126)     // 630
#define NBIAS (VV / 8)           // 1000
#define MEGA_GRID (NG + NWFT + NBIAS + 2)   // 1760 (mult of 4)
#define MEGA_SMEM GRU_SMEM

__global__ void __launch_bounds__(256, 1) __cluster_dims__(4, 1, 1)
mega2(const float* __restrict__ embW, const float* __restrict__ uperm,
      const float* __restrict__ bf1, const float* __restrict__ bb1,
      const int* __restrict__ tokens, __half* __restrict__ hcat,
      const __half* __restrict__ w2t, const __half* __restrict__ w1h,
      float* __restrict__ partk, const float* __restrict__ zb,
      const float* __restrict__ b1, const float* __restrict__ b2,
      float* __restrict__ bf)
{
    extern __shared__ __align__(16) unsigned char sm[];
    int b = blockIdx.x;
    if (b < NG) {
        gru_body(sm, embW, uperm, bf1, bb1, tokens, hcat);
    } else if (b < NG + NWFT) {
        int w = b - NG;
        int kz = w / 126, t = w % 126;
        gemm_body(w2t + (size_t)kz * KC, VV,
                  w1h + (size_t)kz * KC, VV,
                  zb, partk + (size_t)kz * VV * 2 * UU,
                  VV, 2 * UU, KC, t, sm);
    } else if (b < NG + NWFT + NBIAS) {
        int nb = b - NG - NWFT;
        int n = nb * 8 + (threadIdx.x >> 5);
        int lane = threadIdx.x & 31;
        const __half2* row = (const __half2*)(w2t + (size_t)n * VV);
        const float2* b1p = (const float2*)b1;
        float acc = 0.f;
#pragma unroll 5
        for (int i = 0; i < VV / 64; i++) {
            int idx = i * 32 + lane;
            float2 f = __half22float2(row[idx]);
            float2 bb = b1p[idx];
            acc += bb.x * f.x + bb.y * f.y;
        }
#pragma unroll
        for (int off = 16; off > 0; off >>= 1)
            acc += __shfl_xor_sync(0xFFFFFFFF, acc, off);
        if (lane == 0) bf[n] = acc + b2[n];
    }
}

// ---------------- host launcher ----------------------------------------------
extern "C" void kernel_launch(void* const* d_in, const int* in_sizes, int n_in,
                              void* d_out, int out_size)
{
    const int*   tokens = (const int*)d_in[0];
    const float* emb    = (const float*)d_in[1];
    const float* W_f    = (const float*)d_in[2];
    const float* U_f    = (const float*)d_in[3];
    const float* b_f    = (const float*)d_in[4];
    const float* W_b    = (const float*)d_in[5];
    const float* U_b    = (const float*)d_in[6];
    const float* b_b    = (const float*)d_in[7];
    const float* W1     = (const float*)d_in[8];
    const float* b1     = (const float*)d_in[9];
    const float* W2     = (const float*)d_in[10];
    const float* b2     = (const float*)d_in[11];
    float* out = (float*)d_out;

    __half *w1h, *w2t, *embh, *wcatt, *hcat, *wfth;
    float *bcat, *embw, *bfv, *uperm, *partk, *zb;
    cudaGetSymbolAddress((void**)&w1h,   g_w1h);
    cudaGetSymbolAddress((void**)&w2t,   g_w2t);
    cudaGetSymbolAddress((void**)&embh,  g_embh);
    cudaGetSymbolAddress((void**)&wcatt, g_wcatt);
    cudaGetSymbolAddress((void**)&bcat,  g_bcat);
    cudaGetSymbolAddress((void**)&embw,  g_embw);
    cudaGetSymbolAddress((void**)&hcat,  g_hcat);
    cudaGetSymbolAddress((void**)&wfth,  g_wfth);
    cudaGetSymbolAddress((void**)&bfv,   g_bf);
    cudaGetSymbolAddress((void**)&uperm, g_uperm);
    cudaGetSymbolAddress((void**)&partk, g_partk);
    cudaGetSymbolAddress((void**)&zb,    g_zb);

    cudaFuncSetAttribute(gemm_h0, cudaFuncAttributeMaxDynamicSharedMemorySize, HGE_SMEM);
    cudaFuncSetAttribute(mega2,   cudaFuncAttributeMaxDynamicSharedMemorySize, MEGA_SMEM);

    // 1) fused prep (W1->fp16, emb->fp16, wcat^T fp16 + bias concat, U permute)
    prep_all<<<(P_TOT + 255) / 256, 256>>>(W1, w1h, emb, embh,
                                           W_f, W_b, b_f, b_b, wcatt, bcat,
                                           U_f, U_b, uperm);
    // 2) W2 -> fp16(W2^T)
    transpose_f16<<<dim3(VV / 32, VV / 32), dim3(32, 8)>>>(W2, w2t);

    // 3) embW = emb @ [W_f|W_b] + bias   [8000, 1536] fp32 (GRU input)
    {
        int mtiles = (VV + HBM_ - 1) / HBM_;     // 63
        int ntiles = H6 / HBN_;                  // 6
        gemm_h0<<<mtiles * ntiles, 256, HGE_SMEM>>>(embh, DD, wcatt, DD,
                                                    bcat, embw, VV, H6, DD);
    }

    // 4) mega2: GRU (128 cluster CTAs) || WfT split-K GEMM (630) || bias (1000)
    mega2<<<MEGA_GRID, 256, MEGA_SMEM>>>(embw, uperm, b_f + H3, b_b + H3,
                                         tokens, hcat,
                                         w2t, w1h, partk, zb, b1, b2, bfv);

    // 5) reduce split-K partials -> fp16 WfT [8000,512]
    wf_reduce<<<(VV * 2 * UU / 4 + 255) / 256, 256>>>(partk, wfth);

    // 6) logits = hcat @ Wf + bf -> output
    {
        int mtiles = MR / HBM_;                  // 64
        int ntiles = (VV + HBN_ - 1) / HBN_;     // 32
        gemm_h0<<<mtiles * ntiles, 256, HGE_SMEM>>>(hcat, 2 * UU, wfth, 2 * UU,
                                                    bfv, out, MR, VV, 2 * UU);
    }
}

// round 13
// speedup vs baseline: 2.7906x; 1.0414x over previous
#include <cuda_runtime.h>
#include <cuda_fp16.h>
#include <cstdint>

#define VV 8000
#define DD 128
#define UU 256
#define BB 32
#define SS 256
#define H3 768
#define H6 1536
#define MR 8192   // B*S
#define KC 1600   // WfT split-K chunk (x5)
#define NSPLIT 5

// ---------------- scratch (static device allocations; no cudaMalloc) ---------
__device__ __align__(128) __half g_w1h[2 * UU * VV];    // fp16(W1) [512,8000]
__device__ __align__(128) __half g_w2t[VV * VV];        // fp16(W2^T) [8000,8000]
__device__ __align__(128) __half g_embh[VV * DD];       // fp16(emb)
__device__ __align__(128) __half g_wcatt[H6 * DD];      // fp16([W_f|W_b]^T)
__device__ __align__(128) float  g_bcat[H6];
__device__ __align__(128) float  g_embw[VV * H6];       // emb proj + bias (fp32)
__device__ __align__(128) __half g_hcat[MR * 2 * UU];   // fp16 GRU outputs
__device__ __align__(128) __half g_wfth[VV * 2 * UU];   // fp16((W1@W2)^T) [8000,512]
__device__ __align__(128) float  g_partk[NSPLIT * VV * 2 * UU];  // split-K partials
__device__ __align__(128) float  g_bf[VV];
__device__ __align__(128) float  g_zb[2 * UU];          // zero bias (never written)
__device__ __align__(128) float  g_uperm[2 * 4 * UU * 192];

// packed f32x2 helpers (sm_103a)
__device__ __forceinline__ unsigned long long pack2(float x, float y) {
    unsigned long long r;
    asm("mov.b64 %0, {%1,%2};" : "=l"(r) : "f"(x), "f"(y));
    return r;
}
__device__ __forceinline__ float2 unpack2(unsigned long long v) {
    float2 r;
    asm("mov.b64 {%0,%1}, %2;" : "=f"(r.x), "=f"(r.y) : "l"(v));
    return r;
}
#define FMA2(acc, a, b) \
    asm("fma.rn.f32x2 %0, %1, %2, %0;" : "+l"(acc) : "l"(a), "l"(b))

// DSMEM / cluster helpers
__device__ __forceinline__ uint32_t mapa_u32(uint32_t laddr, uint32_t rank) {
    uint32_t r;
    asm("mapa.shared::cluster.u32 %0, %1, %2;" : "=r"(r) : "r"(laddr), "r"(rank));
    return r;
}
#define CLUSTER_ARRIVE() asm volatile("barrier.cluster.arrive.aligned;" ::: "memory")
#define CLUSTER_WAIT()   asm volatile("barrier.cluster.wait.aligned;" ::: "memory")

// async remote store with mbarrier tx completion (sm_90+)
#define ST_ASYNC_U64(raddr, v, rmbar) \
    asm volatile("st.async.shared::cluster.mbarrier::complete_tx::bytes.u64 [%0], %1, [%2];" \
                 :: "r"(raddr), "l"(v), "r"(rmbar) : "memory")

#define MBARRIER_INIT(addr, cnt) \
    asm volatile("mbarrier.init.shared.b64 [%0], %1;" :: "r"((uint32_t)(addr)), "r"((uint32_t)(cnt)) : "memory")
#define MBARRIER_EXPECT_TX(addr, tx) \
    asm volatile("mbarrier.arrive.expect_tx.shared.b64 _, [%0], %1;" \
                 :: "r"((uint32_t)(addr)), "r"((uint32_t)(tx)) : "memory")
#define MBARRIER_WAIT_PARITY(addr, par) do {                                   \
    uint32_t _m = (uint32_t)(addr); uint32_t _p = (uint32_t)(par);             \
    asm volatile(                                                              \
        "{\n\t.reg .pred P1;\n\t"                                              \
        "WL_%=:\n\t"                                                           \
        "mbarrier.try_wait.parity.acquire.cta.shared::cta.b64 P1, [%0], %1, 0x989680;\n\t" \
        "@P1 bra.uni WD_%=;\n\t"                                               \
        "bra.uni WL_%=;\n\t"                                                   \
        "WD_%=:\n\t}"                                                          \
        :: "r"(_m), "r"(_p) : "memory");                                       \
} while (0)

// ---------------- fused prep + W2-transpose kernel ----------------------------
#define P_W1   (2 * UU * VV / 4)
#define P_EMB  (VV * DD / 4)
#define P_WCAT (H6 * DD)
#define P_U    (2 * 4 * UU * 192)
#define P_TOT  (P_W1 + P_EMB + P_WCAT + P_U)
#define TR_BLK (VV / 32 * VV / 32)     // 62500
#define PREP_BLK ((P_TOT + 255) / 256)
#define PREPTR_GRID (TR_BLK + PREP_BLK)

__global__ void __launch_bounds__(256) prep_tr(
    const float* __restrict__ W2, __half* __restrict__ w2t,
    const float* __restrict__ W1, __half* __restrict__ w1h,
    const float* __restrict__ emb, __half* __restrict__ embh,
    const float* __restrict__ Wf_, const float* __restrict__ Wb_,
    const float* __restrict__ bfb, const float* __restrict__ bbb,
    __half* __restrict__ wcatt, float* __restrict__ bcat,
    const float* __restrict__ Uf, const float* __restrict__ Ub,
    float* __restrict__ uperm)
{
    __shared__ float t[32][33];
    int b = blockIdx.x;
    int tid = threadIdx.x;
    if (b < TR_BLK) {
        // W2 transpose tile -> fp16(W2^T)
        int bx = (b % (VV / 32)) * 32;
        int by = (b / (VV / 32)) * 32;
        int x = tid & 31, y0 = tid >> 5;   // y0 0..7
#pragma unroll
        for (int dy = 0; dy < 32; dy += 8)
            t[y0 + dy][x] = W2[(size_t)(by + y0 + dy) * VV + bx + x];
        __syncthreads();
#pragma unroll
        for (int dy = 0; dy < 32; dy += 8)
            w2t[(size_t)(bx + y0 + dy) * VV + by + x] = __float2half_rn(t[x][y0 + dy]);
        return;
    }
    int i = (b - TR_BLK) * 256 + tid;
    if (i < P_W1) {
        float4 v = ((const float4*)W1)[i];
        __half2 h0 = __floats2half2_rn(v.x, v.y);
        __half2 h1 = __floats2half2_rn(v.z, v.w);
        uint2 r;
        r.x = *reinterpret_cast<uint32_t*>(&h0);
        r.y = *reinterpret_cast<uint32_t*>(&h1);
        ((uint2*)w1h)[i] = r;
        return;
    }
    i -= P_W1;
    if (i < P_EMB) {
        float4 v = ((const float4*)emb)[i];
        __half2 h0 = __floats2half2_rn(v.x, v.y);
        __half2 h1 = __floats2half2_rn(v.z, v.w);
        uint2 r;
        r.x = *reinterpret_cast<uint32_t*>(&h0);
        r.y = *reinterpret_cast<uint32_t*>(&h1);
        ((uint2*)embh)[i] = r;
        return;
    }
    i -= P_EMB;
    if (i < P_WCAT) {
        int n = i / DD, k = i % DD;
        float v = (n < H3) ? Wf_[k * H3 + n] : Wb_[k * H3 + (n - H3)];
        wcatt[i] = __float2half_rn(v);
        if (i < H6)
            bcat[i] = (i < H3) ? bfb[i] : bbb[i - H3];
        return;
    }
    i -= P_WCAT;
    if (i < P_U) {
        int c = i % 192;
        int k = (i / 192) % UU;
        int r = (i / (192 * UU)) % 4;
        int dir = i / (192 * UU * 4);
        const float* Um = dir ? Ub : Uf;
        int col = (c < 64) ? (64 * r + c)
                : (c < 128) ? (UU + 64 * r + (c - 64))
                            : (2 * UU + 64 * r + (c - 128));
        uperm[i] = Um[k * H3 + col];
    }
}

// split-K reduce: wfth = fp16(sum of NSPLIT partials)
__global__ void wf_reduce(const float* __restrict__ partk, __half* __restrict__ wfth) {
    int i = blockIdx.x * 256 + threadIdx.x;
    const int n4 = VV * 2 * UU / 4;
    if (i >= n4) return;
    float4 s = ((const float4*)partk)[i];
#pragma unroll
    for (int z = 1; z < NSPLIT; z++) {
        float4 v = ((const float4*)(partk + (size_t)z * VV * 2 * UU))[i];
        s.x += v.x; s.y += v.y; s.z += v.z; s.w += v.w;
    }
    __half2 h0 = __floats2half2_rn(s.x, s.y);
    __half2 h1 = __floats2half2_rn(s.z, s.w);
    uint2 r;
    r.x = *reinterpret_cast<uint32_t*>(&h0);
    r.y = *reinterpret_cast<uint32_t*>(&h1);
    ((uint2*)wfth)[i] = r;
}

// ---------------- fp16 GEMM body (mma.sync m16n8k16, fp32 accum) --------------
#define HBM_ 128
#define HBN_ 256
#define HBK_ 32
#define HNST 4
#define HROWB 80
#define HASB (HBM_ * HROWB)
#define HBSB (HBN_ * HROWB)
#define HSTG (HASB + HBSB)
#define HGE_SMEM (HNST * HSTG)

__device__ __forceinline__ void gemm_body(
    const __half* __restrict__ A, int lda,
    const __half* __restrict__ Bt, int ldb,
    const float* __restrict__ bias, float* __restrict__ C,
    int M, int N, int K, int tile, unsigned char* sm)
{
    int ntiles = (N + HBN_ - 1) / HBN_;
    int mt = tile / ntiles, nt = tile % ntiles;
    int m0 = mt * HBM_, n0 = nt * HBN_;

    int tid = threadIdx.x;
    int lane = tid & 31;
    int wid = tid >> 5;
    int wm = wid >> 2;
    int wn = wid & 3;
    int g = lane >> 2;
    int t4 = lane & 3;

    uint32_t sbase = (uint32_t)__cvta_generic_to_shared(sm);

    float acc[4][8][4];
#pragma unroll
    for (int a = 0; a < 4; a++)
#pragma unroll
        for (int b = 0; b < 8; b++)
#pragma unroll
            for (int c = 0; c < 4; c++) acc[a][b][c] = 0.f;

    const int KT = K / HBK_;

    auto issue = [&](int kt, int slot) {
        int k0 = kt * HBK_;
        uint32_t ab = sbase + slot * HSTG;
        uint32_t bb = ab + HASB;
#pragma unroll
        for (int i = 0; i < 2; i++) {
            int ch = tid + i * 256;
            int r = ch >> 2, c16 = ch & 3;
            int ra = m0 + r; if (ra >= M) ra = M - 1;
            const __half* src = A + (size_t)ra * lda + k0 + c16 * 8;
            uint32_t dst = ab + (uint32_t)(r * HROWB + c16 * 16);
            asm volatile("cp.async.cg.shared.global [%0],[%1],16;\n" :: "r"(dst), "l"(src));
        }
#pragma unroll
        for (int i = 0; i < 4; i++) {
            int ch = tid + i * 256;
            int r = ch >> 2, c16 = ch & 3;
            int nb = n0 + r;
            int sz = (nb < N) ? 16 : 0;
            if (nb >= N) nb = N - 1;
            const __half* src = Bt + (size_t)nb * ldb + k0 + c16 * 8;
            uint32_t dst = bb + (uint32_t)(r * HROWB + c16 * 16);
            asm volatile("cp.async.cg.shared.global [%0],[%1],16,%2;\n" :: "r"(dst), "l"(src), "r"(sz));
        }
        asm volatile("cp.async.commit_group;\n");
    };

    auto docompute = [&](int slot) {
        const unsigned char* As = sm + slot * HSTG;
        const unsigned char* Bs = As + HASB;
#pragma unroll
        for (int kk = 0; kk < 2; kk++) {
            int kb = kk * 32 + t4 * 4;
            uint32_t af[4][4];
#pragma unroll
            for (int mi = 0; mi < 4; mi++) {
                int row = wm * 64 + mi * 16 + g;
                const unsigned char* p = As + row * HROWB + kb;
                af[mi][0] = *(const uint32_t*)(p);
                af[mi][1] = *(const uint32_t*)(p + 8 * HROWB);
                af[mi][2] = *(const uint32_t*)(p + 16);
                af[mi][3] = *(const uint32_t*)(p + 8 * HROWB + 16);
            }
            uint32_t bf[8][2];
#pragma unroll
            for (int ni = 0; ni < 8; ni++) {
                int nr = wn * 64 + ni * 8 + g;
                const unsigned char* p = Bs + nr * HROWB + kb;
                bf[ni][0] = *(const uint32_t*)(p);
                bf[ni][1] = *(const uint32_t*)(p + 16);
            }
#pragma unroll
            for (int mi = 0; mi < 4; mi++)
#pragma unroll
                for (int ni = 0; ni < 8; ni++) {
                    asm volatile(
                        "mma.sync.aligned.m16n8k16.row.col.f32.f16.f16.f32 "
                        "{%0,%1,%2,%3},{%4,%5,%6,%7},{%8,%9},{%0,%1,%2,%3};\n"
                        : "+f"(acc[mi][ni][0]), "+f"(acc[mi][ni][1]),
                          "+f"(acc[mi][ni][2]), "+f"(acc[mi][ni][3])
                        : "r"(af[mi][0]), "r"(af[mi][1]), "r"(af[mi][2]), "r"(af[mi][3]),
                          "r"(bf[ni][0]), "r"(bf[ni][1]));
                }
        }
    };

    issue(0, 0);
    if (KT > 1) issue(1, 1);
    if (KT > 2) issue(2, 2);

#pragma unroll 1
    for (int kt = 0; kt < KT; kt++) {
        if (kt + 1 < KT) {
            asm volatile("cp.async.wait_group %0;\n" :: "n"(HNST - 2));
        } else {
            asm volatile("cp.async.wait_group 0;\n");
        }
        __syncthreads();
        if (kt + HNST - 1 < KT)
            issue(kt + HNST - 1, (kt + HNST - 1) & (HNST - 1));
        docompute(kt & (HNST - 1));
    }

#pragma unroll
    for (int ni = 0; ni < 8; ni++) {
        int c = n0 + wn * 64 + ni * 8 + t4 * 2;
        if (c >= N) continue;
        float b0v = bias[c], b1v = bias[c + 1];
#pragma unroll
        for (int mi = 0; mi < 4; mi++) {
            int r = m0 + wm * 64 + mi * 16 + g;
            if (r >= M) continue;
            *reinterpret_cast<float2*>(&C[(size_t)r * N + c]) =
                make_float2(acc[mi][ni][0] + b0v, acc[mi][ni][1] + b1v);
            if (r + 8 < M)
                *reinterpret_cast<float2*>(&C[(size_t)(r + 8) * N + c]) =
                    make_float2(acc[mi][ni][2] + b0v, acc[mi][ni][3] + b1v);
        }
    }
}

// standalone GEMM (final logits)
__global__ void __launch_bounds__(256) gemm_h0(
    const __half* __restrict__ A, int lda, const __half* __restrict__ Bt, int ldb,
    const float* __restrict__ bias, float* __restrict__ C,
    int M, int N, int K)
{
    extern __shared__ __align__(16) unsigned char sm[];
    gemm_body(A, lda, Bt, ldb, bias, C, M, N, K, blockIdx.x, sm);
}

// ---------------- megaWE: WfT split-K + embW GEMM + bias fuse -----------------
#define NWFT  (NSPLIT * 126)     // 630
#define NEMB  378                // 63 x 6
#define NBIAS (VV / 8)           // 1000
#define MWE_GRID (NWFT + NEMB + NBIAS)

__global__ void __launch_bounds__(256) megaWE(
    const __half* __restrict__ w2t, const __half* __restrict__ w1h,
    float* __restrict__ partk, const float* __restrict__ zb,
    const __half* __restrict__ embh, const __half* __restrict__ wcatt,
    const float* __restrict__ bcat, float* __restrict__ embw,
    const float* __restrict__ b1, const float* __restrict__ b2,
    float* __restrict__ bf)
{
    extern __shared__ __align__(16) unsigned char sm[];
    int b = blockIdx.x;
    if (b < NWFT) {
        int kz = b / 126, t = b % 126;
        gemm_body(w2t + (size_t)kz * KC, VV,
                  w1h + (size_t)kz * KC, VV,
                  zb, partk + (size_t)kz * VV * 2 * UU,
                  VV, 2 * UU, KC, t, sm);
    } else if (b < NWFT + NEMB) {
        gemm_body(embh, DD, wcatt, DD, bcat, embw, VV, H6, DD, b - NWFT, sm);
    } else {
        int nb = b - NWFT - NEMB;
        int n = nb * 8 + (threadIdx.x >> 5);
        int lane = threadIdx.x & 31;
        const __half2* row = (const __half2*)(w2t + (size_t)n * VV);
        const float2* b1p = (const float2*)b1;
        float acc = 0.f;
#pragma unroll 5
        for (int i = 0; i < VV / 64; i++) {
            int idx = i * 32 + lane;
            float2 f = __half22float2(row[idx]);
            float2 bb = b1p[idx];
            acc += bb.x * f.x + bb.y * f.y;
        }
#pragma unroll
        for (int off = 16; off > 0; off >>= 1)
            acc += __shfl_xor_sync(0xFFFFFFFF, acc, off);
        if (lane == 0) bf[n] = acc + b2[n];
    }
}

// ---------------- GRU: 384 threads, 8-way k-split, st.async sync --------------
#define GRU_THREADS 384
#define GRU_SM_US   (UU * 192 * 4)              // 196608
#define GRU_SM_PART (16 * 192 * 4)              // 12288
#define GRU_SM_H    (2 * 2 * UU * 8)            // 8192
#define GRU_SMEM    (GRU_SM_US + GRU_SM_PART + GRU_SM_H + 16)
#define UREG 20

__global__ void __launch_bounds__(GRU_THREADS, 1) __cluster_dims__(4, 1, 1)
gru_scan(const float* __restrict__ embW, const float* __restrict__ uperm,
         const float* __restrict__ bf1, const float* __restrict__ bb1,
         const int* __restrict__ tokens, __half* __restrict__ hcat)
{
    extern __shared__ __align__(16) unsigned char smraw[];
    float* Us   = (float*)smraw;
    float* part = (float*)(smraw + GRU_SM_US);
    unsigned long long* hbuf =
        (unsigned long long*)(smraw + GRU_SM_US + GRU_SM_PART);
    uint32_t mb0 = (uint32_t)__cvta_generic_to_shared(smraw + GRU_SM_US + GRU_SM_PART + GRU_SM_H);

    int tid  = threadIdx.x;
    int cid  = blockIdx.x >> 2;
    int rank = blockIdx.x & 3;
    int bp   = cid & 15;
    int dir  = cid >> 4;
    int b0   = bp * 2;
    const float* bv = dir ? bb1 : bf1;

    {
        const float4* src = (const float4*)(uperm + (size_t)(dir * 4 + rank) * UU * 192);
        float4* dst = (float4*)Us;
        for (int i = tid; i < UU * 192 / 4; i += GRU_THREADS) dst[i] = src[i];
        for (int i = tid; i < 2 * 2 * UU; i += GRU_THREADS) hbuf[i] = 0ull;
    }
    if (tid == 0) { MBARRIER_INIT(mb0, 1); MBARRIER_INIT(mb0 + 8, 1); }
    __syncthreads();
    CLUSTER_ARRIVE();
    CLUSTER_WAIT();

    int kc = tid / 48;     // 0..7: k-range of 32
    int ct = tid % 48;     // 2 col-pairs (4 cols)
    int k0 = kc * 32;

    const ulonglong2* U2 = (const ulonglong2*)Us;
    ulonglong2 ur[UREG];
#pragma unroll
    for (int kk = 0; kk < UREG; kk++)
        ur[kk] = U2[(size_t)(k0 + kk) * 48 + ct];

    int jj = tid & 63;
    int ub = (tid >> 6) & 1;
    int j  = rank * 64 + jj;
    float bz = 0.f, br = 0.f, bh = 0.f;
    if (tid < 128) { bz = bv[j]; br = bv[UU + j]; bh = bv[2 * UU + j]; }

    uint32_t hl = (uint32_t)__cvta_generic_to_shared(hbuf);
    uint32_t hpeer[4], mpeer[4];
#pragma unroll
    for (int r = 0; r < 4; r++) {
        hpeer[r] = mapa_u32(hl, r);
        mpeer[r] = mapa_u32(mb0, r);
    }

    int ph0 = 0, ph1 = 0;

    for (int i = 0; i < SS; i++) {
        int p = i & 1;
        if (tid == 0 && i < SS - 1)
            MBARRIER_EXPECT_TX(mb0 + (p ^ 1) * 8, 4096);

        float pz = 0.f, pr = 0.f, phx = 0.f; int tk = 1;
        size_t rb = 0;
        if (tid < 128) {
            int s = dir ? (SS - 1 - i) : i;
            rb = (size_t)(b0 + ub) * SS + s;
            tk = tokens[rb];
            const float* xr = embW + (size_t)tk * H6 + dir * H3;
            pz = xr[j]; pr = xr[UU + j]; phx = xr[2 * UU + j];
        }

        if (i > 0) {
            if (p == 0) { MBARRIER_WAIT_PARITY(mb0,     ph0); ph0 ^= 1; }
            else        { MBARRIER_WAIT_PARITY(mb0 + 8, ph1); ph1 ^= 1; }
        }

        {
            unsigned long long a00 = 0, a01 = 0, a10 = 0, a11 = 0;
            const ulonglong2* h0 = (const ulonglong2*)(hbuf + (p * 2 + 0) * UU) + kc * 16;
            const ulonglong2* h1 = (const ulonglong2*)(hbuf + (p * 2 + 1) * UU) + kc * 16;
            // register part: k = k0 .. k0+UREG (10 pairs)
#pragma unroll
            for (int kk = 0; kk < UREG / 2; kk++) {
                ulonglong2 uA = ur[2 * kk];
                ulonglong2 uB = ur[2 * kk + 1];
                ulonglong2 hA = h0[kk];
                ulonglong2 hB = h1[kk];
                FMA2(a00, uA.x, hA.x); FMA2(a01, uA.y, hA.x);
                FMA2(a10, uA.x, hB.x); FMA2(a11, uA.y, hB.x);
                FMA2(a00, uB.x, hA.y); FMA2(a01, uB.y, hA.y);
                FMA2(a10, uB.x, hB.y); FMA2(a11, uB.y, hB.y);
            }
            // smem part: k = k0+UREG .. k0+32 (6 pairs)
            const ulonglong2* up = U2 + (size_t)(k0 + UREG) * 48 + ct;
#pragma unroll
            for (int kk = UREG / 2; kk < 16; kk++) {
                ulonglong2 uA = up[0];
                ulonglong2 uB = up[48];
                up += 96;
                ulonglong2 hA = h0[kk];
                ulonglong2 hB = h1[kk];
                FMA2(a00, uA.x, hA.x); FMA2(a01, uA.y, hA.x);
                FMA2(a10, uA.x, hB.x); FMA2(a11, uA.y, hB.x);
                FMA2(a00, uB.x, hA.y); FMA2(a01, uB.y, hA.y);
                FMA2(a10, uB.x, hB.y); FMA2(a11, uB.y, hB.y);
            }
            float2 p00 = unpack2(a00), p01 = unpack2(a01);
            float2 p10 = unpack2(a10), p11 = unpack2(a11);
            ((float4*)(part + (kc * 2 + 0) * 192))[ct] = make_float4(p00.x, p00.y, p01.x, p01.y);
            ((float4*)(part + (kc * 2 + 1) * 192))[ct] = make_float4(p10.x, p10.y, p11.x, p11.y);
        }
        __syncthreads();

        if (tid < 128) {
            float iz = 0.f, ir = 0.f, ih = 0.f;
#pragma unroll
            for (int q = 0; q < 8; q++) {
                const float* pr_ = part + (2 * q + ub) * 192;
                iz += pr_[jj];
                ir += pr_[64 + jj];
                ih += pr_[128 + jj];
            }

            float hold = ((const float*)&hbuf[(p * 2 + ub) * UU + j])[0];
            float z = 1.f / (1.f + __expf(-(pz + iz + bz)));
            float g = 1.f / (1.f + __expf(-(pr + ir + br)));
            float c = tanhf(phx + g * (ih + bh));
            float hn = z * hold + (1.f - z) * c;
            if (tk == 0) hn = hold;

            if (i < SS - 1) {
                unsigned long long hd = pack2(hn, hn);
                uint32_t off = (uint32_t)(((p ^ 1) * 2 + ub) * UU + j) * 8u;
                uint32_t mboff = (uint32_t)((p ^ 1) * 8);
#pragma unroll
                for (int r = 0; r < 4; r++)
                    ST_ASYNC_U64(hpeer[r] + off, hd, mpeer[r] + mboff);
            }
            hcat[rb * (2 * UU) + dir * UU + j] = __float2half_rn(hn);
        }
        // part[] reuse ordered through the mbarrier (next-step wait requires
        // all CTAs' st.async, which data-depend on this step's part[] reads)
    }
    CLUSTER_ARRIVE();
    CLUSTER_WAIT();
}

// ---------------- host launcher ----------------------------------------------
extern "C" void kernel_launch(void* const* d_in, const int* in_sizes, int n_in,
                              void* d_out, int out_size)
{
    const int*   tokens = (const int*)d_in[0];
    const float* emb    = (const float*)d_in[1];
    const float* W_f    = (const float*)d_in[2];
    const float* U_f    = (const float*)d_in[3];
    const float* b_f    = (const float*)d_in[4];
    const float* W_b    = (const float*)d_in[5];
    const float* U_b    = (const float*)d_in[6];
    const float* b_b    = (const float*)d_in[7];
    const float* W1     = (const float*)d_in[8];
    const float* b1     = (const float*)d_in[9];
    const float* W2     = (const float*)d_in[10];
    const float* b2     = (const float*)d_in[11];
    float* out = (float*)d_out;

    __half *w1h, *w2t, *embh, *wcatt, *hcat, *wfth;
    float *bcat, *embw, *bfv, *uperm, *partk, *zb;
    cudaGetSymbolAddress((void**)&w1h,   g_w1h);
    cudaGetSymbolAddress((void**)&w2t,   g_w2t);
    cudaGetSymbolAddress((void**)&embh,  g_embh);
    cudaGetSymbolAddress((void**)&wcatt, g_wcatt);
    cudaGetSymbolAddress((void**)&bcat,  g_bcat);
    cudaGetSymbolAddress((void**)&embw,  g_embw);
    cudaGetSymbolAddress((void**)&hcat,  g_hcat);
    cudaGetSymbolAddress((void**)&wfth,  g_wfth);
    cudaGetSymbolAddress((void**)&bfv,   g_bf);
    cudaGetSymbolAddress((void**)&uperm, g_uperm);
    cudaGetSymbolAddress((void**)&partk, g_partk);
    cudaGetSymbolAddress((void**)&zb,    g_zb);

    cudaFuncSetAttribute(megaWE,  cudaFuncAttributeMaxDynamicSharedMemorySize, HGE_SMEM);
    cudaFuncSetAttribute(gemm_h0, cudaFuncAttributeMaxDynamicSharedMemorySize, HGE_SMEM);
    cudaFuncSetAttribute(gru_scan, cudaFuncAttributeMaxDynamicSharedMemorySize, GRU_SMEM);

    // 1) fused prep: W2 transpose (fp16) + fp16 conversions + concat + U permute
    prep_tr<<<PREPTR_GRID, 256>>>(W2, w2t, W1, w1h, emb, embh,
                                  W_f, W_b, b_f, b_b, wcatt, bcat,
                                  U_f, U_b, uperm);

    // 2) megaWE: WfT split-K GEMM (630) + embW GEMM (378) + bias fuse (1000)
    megaWE<<<MWE_GRID, 256, HGE_SMEM>>>(w2t, w1h, partk, zb,
                                        embh, wcatt, bcat, embw,
                                        b1, b2, bfv);

    // 3) reduce split-K partials -> fp16 WfT [8000,512]
    wf_reduce<<<(VV * 2 * UU / 4 + 255) / 256, 256>>>(partk, wfth);

    // 4) clustered bidirectional GRU scan (384 threads, 12 warps)
    gru_scan<<<128, GRU_THREADS, GRU_SMEM>>>(embw, uperm, b_f + H3, b_b + H3,
                                             tokens, hcat);

    // 5) logits = hcat @ Wf + bf -> output
    {
        int mtiles = MR / HBM_;                  // 64
        int ntiles = (VV + HBN_ - 1) / HBN_;     // 32
        gemm_h0<<<mtiles * ntiles, 256, HGE_SMEM>>>(hcat, 2 * UU, wfth, 2 * UU,
                                                    bfv, out, MR, VV, 2 * UU);
    }
}